// round 4
// baseline (speedup 1.0000x reference)
#include <cuda_runtime.h>
#include <math.h>

#define N3INV (1.0f/262144.0f)
typedef unsigned long long u64;

// ---------------- scratch (static device memory; no allocations) ----------------
__device__ float2 g_A [8*16*64*64*12];   // 50 MB: fwd T out [bc*64+x][y*12+k]; inv-Y out (same layout)
__device__ float2 g_Bf[8*16*64*24*12];   // 19 MB: fwd Y out [slab][ky*12+kz]; reused inv-X out [(bo*24+ky)*64+x][kz]
__device__ float2 g_D [8*16*24*24*12];   //  7 MB: modes [((bo)*24+ky)*24+kx][kz]
__device__ float2 g_W [24*24*12*16*16];  // 14 MB: repacked weights, mode-major
__device__ u64    g_twTpk[12*32];        // fwd T: (c, -s) packed
__device__ float2 g_twTi2[12*32];        // inv T: (A, B) = (2c/N^3, -2s/N^3); k=0: (1/N^3, 0)
__device__ u64    g_twXc[24*33];         // fwd X/Y: (c, c)   [padded stride 33]
__device__ u64    g_twXs[24*33];         // fwd X/Y: (s, s)
__device__ float2 g_twT1[24*33];         // inv X/Y: (c, s)
__device__ u64    g_twT2i[24*33];        // inv X/Y: (-s, c)

// ---------------- f32x2 packed helpers ----------------
__device__ __forceinline__ u64 pk2(float lo, float hi){
    u64 r; asm("mov.b64 %0, {%1,%2};" : "=l"(r) : "f"(lo), "f"(hi)); return r;
}
__device__ __forceinline__ void fma2(u64& d, u64 a, u64 b){
    asm("fma.rn.f32x2 %0, %1, %2, %0;" : "+l"(d) : "l"(a), "l"(b));
}
__device__ __forceinline__ float2 unpk2(u64 v){
    float2 f; asm("mov.b64 {%0,%1}, %2;" : "=f"(f.x), "=f"(f.y) : "l"(v)); return f;
}

// ---------------- init: twiddle tables ----------------
__global__ void k_init() {
    int idx = blockIdx.x * blockDim.x + threadIdx.x;
    if (idx < 384) {
        int k = idx >> 5, t = idx & 31;
        float s, c;
        sincospif((float)((k * t) & 63) / 32.0f, &s, &c);
        g_twTpk[idx] = pk2(c, -s);
        g_twTi2[idx] = (k == 0) ? make_float2(N3INV, 0.0f)
                                : make_float2(2.0f*c*N3INV, -2.0f*s*N3INV);
    } else if (idx < 384 + 768) {
        int r = idx - 384;
        int j = r >> 5, u = r & 31;
        int f = (j < 12) ? j : j + 40;   // freqs 0..11, 52..63
        float s, c;
        sincospif((float)((f * u) & 63) / 32.0f, &s, &c);
        int a = j*33 + u;
        g_twXc[a]  = pk2(c, c);
        g_twXs[a]  = pk2(s, s);
        g_twT1[a]  = make_float2(c, s);
        g_twT2i[a] = pk2(-s, c);
    }
}

// ---------------- repack: register transpose (verified in R3) ----------------
__global__ void __launch_bounds__(256) k_repack2(const float* __restrict__ w1, const float* __restrict__ w2,
                                                 const float* __restrict__ w3, const float* __restrict__ w4) {
    int jx = blockIdx.x / 12, jy = blockIdx.x % 12;
    int tid = threadIdx.x;
#pragma unroll
    for (int q = 0; q < 4; q++) {
        const float* w = (q == 0) ? w1 : (q == 1) ? w2 : (q == 2) ? w3 : w4;
        const float4* src = (const float4*)(w + ((size_t)tid*1728 + (jx*12 + jy)*12)*2);
        float2 r[12];
#pragma unroll
        for (int j = 0; j < 6; j++) {
            float4 v = src[j];
            r[2*j]   = make_float2(v.x, v.y);
            r[2*j+1] = make_float2(v.z, v.w);
        }
        int kxi = jx + ((q & 1) ? 12 : 0);
        int kyi = jy + ((q & 2) ? 12 : 0);
        float2* dst = g_W + ((size_t)(kxi*24 + kyi)*12)*256 + tid;
#pragma unroll
        for (int j = 0; j < 12; j++) dst[j*256] = r[j];
    }
}

// ---------------- K1: real DFT over T (radix-2 in-loop, packed fma2) ----------------
// block = 2 slabs; 128 threads; thread = (slab, y), owns all 12 kz
__global__ void __launch_bounds__(128) k_dft_t(const float* __restrict__ x) {
    __shared__ float sx[2*64*65];
    __shared__ u64 stw[384];
    int slab0 = blockIdx.x * 2;
    const float4* xs = (const float4*)(x + (size_t)slab0 * 4096);
    for (int i = threadIdx.x; i < 2048; i += 128) {
        float4 v = xs[i];
        int sl = i >> 10, r = i & 1023;
        int yy = r >> 4, t4 = (r & 15) * 4;
        float* row = &sx[sl*4160 + yy*65 + t4];
        row[0] = v.x; row[1] = v.y; row[2] = v.z; row[3] = v.w;
    }
    for (int i = threadIdx.x; i < 384; i += 128) stw[i] = g_twTpk[i];
    __syncthreads();

    int sl = threadIdx.x >> 6, yy = threadIdx.x & 63;
    const float* row = &sx[sl*4160 + yy*65];
    u64 acc[12];
#pragma unroll
    for (int k = 0; k < 12; k++) acc[k] = 0ull;
#pragma unroll 4
    for (int t1 = 0; t1 < 32; t1++) {
        float a = row[t1], b = row[t1 + 32];
        float E = a + b, O = a - b;
        u64 pE = pk2(E, E), pO = pk2(O, O);
#pragma unroll
        for (int k = 0; k < 12; k++) fma2(acc[k], stw[k*32 + t1], (k & 1) ? pO : pE);
    }
    float2* dst = g_A + (size_t)(slab0 + sl)*768 + yy*12;
#pragma unroll
    for (int k = 0; k < 12; k++) dst[k] = unpk2(acc[k]);
}

// ---------------- K2: complex DFT over Y (radix-2, tiled 3ky x 3kz, packed) ----------------
// block = 4 slabs; 128 threads (32/slab)
__global__ void __launch_bounds__(128) k_dft_y() {
    __shared__ float2 sEO[4*804];        // [slab][p*396 + k*33 + y1]
    __shared__ u64 sc[792], ss[792];
    int slab0 = blockIdx.x * 4;
    for (int i = threadIdx.x; i < 1536; i += 128) {
        int sl = i / 384, r = i % 384;   // r = y1*12 + k
        float2 a = g_A[(size_t)(slab0 + sl)*768 + r];
        float2 b = g_A[(size_t)(slab0 + sl)*768 + 384 + r];
        int k = r % 12, y1 = r / 12;
        sEO[sl*804 + k*33 + y1]       = make_float2(a.x + b.x, a.y + b.y);
        sEO[sl*804 + 396 + k*33 + y1] = make_float2(a.x - b.x, a.y - b.y);
    }
    for (int i = threadIdx.x; i < 792; i += 128) { sc[i] = g_twXc[i]; ss[i] = g_twXs[i]; }
    __syncthreads();

    int u = threadIdx.x & 31, sl = threadIdx.x >> 5;
    int q = u & 3, h = u >> 2;
    int p = h & 1, g4 = h >> 1;
    int k0 = q * 3;
    int ky0 = p + 6 * g4;                // ky = ky0 + 2j, j<3 (same parity)
    const float2* dat = sEO + sl*804 + p*396 + k0*33;
    u64 acc[3][3];
#pragma unroll
    for (int j = 0; j < 3; j++)
#pragma unroll
        for (int z = 0; z < 3; z++) acc[j][z] = 0ull;

#pragma unroll 4
    for (int y1 = 0; y1 < 32; y1++) {
        u64 d1[3], d2[3];
#pragma unroll
        for (int z = 0; z < 3; z++) {
            float2 v = dat[z*33 + y1];
            d1[z] = pk2(v.x, v.y);
            d2[z] = pk2(v.y, -v.x);
        }
#pragma unroll
        for (int j = 0; j < 3; j++) {
            int ky = ky0 + 2*j;
            u64 cp = sc[ky*33 + y1], sp = ss[ky*33 + y1];
#pragma unroll
            for (int z = 0; z < 3; z++) { fma2(acc[j][z], cp, d1[z]); fma2(acc[j][z], sp, d2[z]); }
        }
    }
    float2* dst = g_Bf + (size_t)(slab0 + sl)*288;
#pragma unroll
    for (int j = 0; j < 3; j++) {
        int ky = ky0 + 2*j;
#pragma unroll
        for (int z = 0; z < 3; z++) dst[ky*12 + k0 + z] = unpk2(acc[j][z]);
    }
}

// ---------------- KB: X-DFT (radix-2, kx-pair tile, packed) + spectral 16x16 mix ----------------
// block = (b, ky, kz); 192 threads
__global__ void __launch_bounds__(192) kB() {
    __shared__ float2 sIn[16*66];
    __shared__ float2 sAcc[24*16];
    __shared__ u64 sc[792], ss[792];
    int blk = blockIdx.x;
    int b = blk / 288, r = blk % 288;
    int ky = r / 12, kz = r % 12;
    int tid = threadIdx.x;

    for (int i = tid; i < 1024; i += 192) {
        int c = i >> 6, xx = i & 63;
        sIn[c*66 + xx] = g_Bf[(size_t)((b*16 + c)*64 + xx)*288 + ky*12 + kz];
    }
    for (int i = tid; i < 792; i += 192) { sc[i] = g_twXc[i]; ss[i] = g_twXs[i]; }
    __syncthreads();

    for (int i = tid; i < 512; i += 192) {
        int c = i >> 5, x1 = i & 31;
        float2 a = sIn[c*66 + x1], bb = sIn[c*66 + x1 + 32];
        sIn[c*66 + x1]      = make_float2(a.x + bb.x, a.y + bb.y);
        sIn[c*66 + x1 + 32] = make_float2(a.x - bb.x, a.y - bb.y);
    }
    __syncthreads();

    {   // stage 1: X DFT, thread = (kx-pair g/g+12, c)
        int c = tid & 15, g = tid >> 4;   // g < 12
        int p = g & 1;
        u64 accA = 0ull, accB = 0ull;
        const float2* rowp = &sIn[c*66 + p*32];
#pragma unroll 4
        for (int x1 = 0; x1 < 32; x1++) {
            float2 v = rowp[x1];
            u64 d1 = pk2(v.x, v.y), d2 = pk2(v.y, -v.x);
            fma2(accA, sc[g*33 + x1], d1);        fma2(accA, ss[g*33 + x1], d2);
            fma2(accB, sc[(g+12)*33 + x1], d1);   fma2(accB, ss[(g+12)*33 + x1], d2);
        }
        sAcc[g*16 + c]      = unpk2(accA);
        sAcc[(g+12)*16 + c] = unpk2(accB);
    }
    __syncthreads();
    {   // stage 2: per-mode complex channel mix
        int o = tid & 15, g = tid >> 4;
#pragma unroll
        for (int half = 0; half < 2; half++) {
            int kx = g + half*12;
            const float2* Wp = g_W + ((size_t)((kx*24 + ky)*12 + kz)) * 256;
            float2 acc = make_float2(0.f, 0.f);
#pragma unroll
            for (int i = 0; i < 16; i++) {
                float2 av = sAcc[kx*16 + i];
                float2 w  = Wp[i*16 + o];
                acc.x += av.x*w.x - av.y*w.y;
                acc.y += av.x*w.y + av.y*w.x;
            }
            g_D[(((size_t)(b*16 + o)*24 + ky)*24 + kx)*12 + kz] = acc;
        }
    }
}

// ---------------- KC: inverse X DFT (24 -> 64), parity, tiled 2x x 6kz, packed ----------------
// unit = (bo, ky); 8 units/block; 256 threads
__global__ void __launch_bounds__(256) kC() {
    __shared__ float2 sD[8*292];
    __shared__ u64 sT1[792], sT2[792];
    int unit0 = blockIdx.x * 8;          // unit = bo*24 + ky
    int tid = threadIdx.x;
    for (int i = tid; i < 2304; i += 256) {
        int un = i / 288, r = i % 288;
        sD[un*292 + r] = g_D[(size_t)(unit0 + un)*288 + r];
    }
    for (int i = tid; i < 792; i += 256) { sT1[i] = ((const u64*)g_twT1)[i]; sT2[i] = g_twT2i[i]; }
    __syncthreads();

    int v = tid & 31, un = tid >> 5;
    int x1g = v >> 1, q = v & 1, k0 = q*6;
    const float2* D = sD + un*292;
    u64 Se[2][6], So[2][6];
#pragma unroll
    for (int a = 0; a < 2; a++)
#pragma unroll
        for (int z = 0; z < 6; z++) { Se[a][z] = 0ull; So[a][z] = 0ull; }

#pragma unroll 2
    for (int kx = 0; kx < 24; kx++) {
        u64 e1[6], e2[6];
#pragma unroll
        for (int z = 0; z < 6; z++) {
            float2 d = D[kx*12 + k0 + z];
            e1[z] = pk2(d.x, d.x); e2[z] = pk2(d.y, d.y);
        }
#pragma unroll
        for (int a = 0; a < 2; a++) {
            int x1 = x1g + 16*a;
            u64 t1 = sT1[kx*33 + x1], t2 = sT2[kx*33 + x1];
            if (kx & 1) {
#pragma unroll
                for (int z = 0; z < 6; z++) { fma2(So[a][z], t1, e1[z]); fma2(So[a][z], t2, e2[z]); }
            } else {
#pragma unroll
                for (int z = 0; z < 6; z++) { fma2(Se[a][z], t1, e1[z]); fma2(Se[a][z], t2, e2[z]); }
            }
        }
    }
    float2* base = g_Bf + (size_t)(unit0 + un)*768;   // reuse g_Bf: [(bo*24+ky)*64 + x][kz]
#pragma unroll
    for (int a = 0; a < 2; a++) {
        int x1 = x1g + 16*a;
#pragma unroll
        for (int z = 0; z < 6; z++) {
            float2 se = unpk2(Se[a][z]), so = unpk2(So[a][z]);
            base[(size_t)x1*12 + k0 + z]        = make_float2(se.x + so.x, se.y + so.y);
            base[(size_t)(x1 + 32)*12 + k0 + z] = make_float2(se.x - so.x, se.y - so.y);
        }
    }
}

// ---------------- KYI: inverse Y DFT (24 -> 64), parity, tiled 2y x 6kz, packed ----------------
// unit = (bo, xx); 8 units/block; 256 threads
__global__ void __launch_bounds__(256) k_idft_y2() {
    __shared__ float2 sE[8*292];
    __shared__ u64 sT1[792], sT2[792];
    int unit0 = blockIdx.x * 8;          // unit = bo*64 + xx
    int tid = threadIdx.x;
    for (int i = tid; i < 2304; i += 256) {
        int un = i / 288, r = i % 288;   // r = ky*12 + kz
        int u2 = unit0 + un;
        int bo = u2 >> 6, xx = u2 & 63;
        int ky = r / 12, kz = r % 12;
        sE[un*292 + r] = g_Bf[((size_t)(bo*24 + ky)*64 + xx)*12 + kz];
    }
    for (int i = tid; i < 792; i += 256) { sT1[i] = ((const u64*)g_twT1)[i]; sT2[i] = g_twT2i[i]; }
    __syncthreads();

    int v = tid & 31, un = tid >> 5;
    int y1g = v >> 1, q = v & 1, k0 = q*6;
    const float2* E = sE + un*292;
    u64 Se[2][6], So[2][6];
#pragma unroll
    for (int a = 0; a < 2; a++)
#pragma unroll
        for (int z = 0; z < 6; z++) { Se[a][z] = 0ull; So[a][z] = 0ull; }

#pragma unroll 2
    for (int ky = 0; ky < 24; ky++) {
        u64 e1[6], e2[6];
#pragma unroll
        for (int z = 0; z < 6; z++) {
            float2 d = E[ky*12 + k0 + z];
            e1[z] = pk2(d.x, d.x); e2[z] = pk2(d.y, d.y);
        }
#pragma unroll
        for (int a = 0; a < 2; a++) {
            int y1 = y1g + 16*a;
            u64 t1 = sT1[ky*33 + y1], t2 = sT2[ky*33 + y1];
            if (ky & 1) {
#pragma unroll
                for (int z = 0; z < 6; z++) { fma2(So[a][z], t1, e1[z]); fma2(So[a][z], t2, e2[z]); }
            } else {
#pragma unroll
                for (int z = 0; z < 6; z++) { fma2(Se[a][z], t1, e1[z]); fma2(Se[a][z], t2, e2[z]); }
            }
        }
    }
    float2* base = g_A + (size_t)(unit0 + un)*768;    // [bc*64+x][y*12+k]
#pragma unroll
    for (int a = 0; a < 2; a++) {
        int y1 = y1g + 16*a;
#pragma unroll
        for (int z = 0; z < 6; z++) {
            float2 se = unpk2(Se[a][z]), so = unpk2(So[a][z]);
            base[(size_t)y1*12 + k0 + z]        = make_float2(se.x + so.x, se.y + so.y);
            base[(size_t)(y1 + 32)*12 + k0 + z] = make_float2(se.x - so.x, se.y - so.y);
        }
    }
}

// ---------------- K7: inverse rfft over T (parity, packed) + ReLU + packed 16x16 mix ----------------
// block = (b, x, y-group-of-8); 256 threads; warp per y-line; lane owns t and t+32
__global__ void __launch_bounds__(256) k_ifft_t_mix(const float* __restrict__ lo_w,
                                                    const float* __restrict__ lo_b,
                                                    float* __restrict__ out) {
    __shared__ u64 sF[8*192];            // [slab][c*12+k] as packed (re,im)
    __shared__ u64 sTi[384];
    __shared__ u64 sWq[256];
    __shared__ float sB[16];
    int blk = blockIdx.x;
    int b   = blk >> 9;
    int rr  = blk & 511;
    int xx  = rr >> 3;
    int yy0 = (rr & 7) * 8;

    for (int i = threadIdx.x; i < 1536; i += 256) {
        int sl = i / 192, r2 = i % 192;
        int c = r2 / 12, k = r2 % 12;
        sF[i] = ((const u64*)g_A)[(((size_t)(b*16 + c)*64 + xx)*64 + yy0 + sl)*12 + k];
    }
    for (int i = threadIdx.x; i < 384; i += 256) sTi[i] = ((const u64*)g_twTi2)[i];
    if (threadIdx.x < 256) { float w = lo_w[threadIdx.x]; sWq[threadIdx.x] = pk2(w, w); }
    if (threadIdx.x < 16)  sB[threadIdx.x] = lo_b[threadIdx.x];
    __syncthreads();

    int w    = threadIdx.x >> 5;
    int lane = threadIdx.x & 31;
    int yy   = yy0 + w;
    const u64* F = &sF[w*192];

    u64 aE[16], aO[16];
#pragma unroll
    for (int c = 0; c < 16; c++) { aE[c] = 0ull; aO[c] = 0ull; }
#pragma unroll
    for (int k = 0; k < 12; k++) {
        u64 ti = sTi[k*32 + lane];
#pragma unroll
        for (int c = 0; c < 16; c++) {
            if (k & 1) fma2(aO[c], F[c*12 + k], ti);
            else       fma2(aE[c], F[c*12 + k], ti);
        }
    }
    u64 p[16];
#pragma unroll
    for (int c = 0; c < 16; c++) {
        float2 e = unpk2(aE[c]), o = unpk2(aO[c]);
        float Ev = e.x + e.y, Ov = o.x + o.y;
        p[c] = pk2(fmaxf(Ev + Ov, 0.f), fmaxf(Ev - Ov, 0.f));
    }
#pragma unroll
    for (int o = 0; o < 16; o++) {
        u64 acc = pk2(sB[o], sB[o]);
#pragma unroll
        for (int c = 0; c < 16; c++) fma2(acc, sWq[o*16 + c], p[c]);
        float2 rv = unpk2(acc);
        float* dst = out + ((((size_t)(b*16 + o)*64 + xx)*64 + yy)*64);
        dst[lane]      = rv.x;
        dst[lane + 32] = rv.y;
    }
}

// ---------------- launch ----------------
extern "C" void kernel_launch(void* const* d_in, const int* in_sizes, int n_in,
                              void* d_out, int out_size) {
    const float* x    = (const float*)d_in[0];
    const float* w1   = (const float*)d_in[1];
    const float* w2   = (const float*)d_in[2];
    const float* w3   = (const float*)d_in[3];
    const float* w4   = (const float*)d_in[4];
    const float* lo_w = (const float*)d_in[5];
    const float* lo_b = (const float*)d_in[6];
    float* out = (float*)d_out;

    k_init<<<5, 256>>>();
    k_repack2<<<144, 256>>>(w1, w2, w3, w4);
    k_dft_t<<<4096, 128>>>(x);                       // T 64->12 (radix-2, packed)
    k_dft_y<<<2048, 128>>>();                        // Y 64->24 (radix-2, 3x3 tile, packed)
    kB<<<2304, 192>>>();                             // X 64->24 + channel mix (radix-2, packed)
    kC<<<384, 256>>>();                              // X 24->64 (parity, 2x6 tile, packed)
    k_idft_y2<<<1024, 256>>>();                      // Y 24->64 (parity, 2x6 tile, packed)
    k_ifft_t_mix<<<4096, 256>>>(lo_w, lo_b, out);    // T 12->64 (parity, packed) + relu + 1x1
}

// round 5
// speedup vs baseline: 1.3054x; 1.3054x over previous
#include <cuda_runtime.h>
#include <math.h>

#define N3INV (1.0f/262144.0f)
typedef unsigned long long u64;

// ---------------- scratch (static device memory; no allocations) ----------------
__device__ float2 g_A [8*16*64*64*12];   // 50 MB: fwd T out [slab][y*12+k]; inv-Y out (same)
__device__ float2 g_Bf[8*16*64*24*12];   // 19 MB: fwd Y out [slab][ky*12+kz]; inv-X out [(bo*24+ky)*64+x][kz]
__device__ float2 g_D [8*16*24*24*12];   //  7 MB: modes [((bo)*24+ky)*24+kx][kz]
__device__ float2 g_W [24*24*12*16*16];  // 14 MB: repacked weights, mode-major
__device__ u64    g_twTpk[12*32];        // fwd T: (c, -s) packed
__device__ float2 g_twTi2[12*32];        // inv T: (A, B) = (2c/N^3, -2s/N^3); k=0: (1/N^3, 0)
__device__ float2 g_twXY [24*33];        // fwd X/Y: (c, s)  [padded stride 33]
__device__ u64    g_twI1 [24*33];        // inv X/Y: (c, s) packed
__device__ u64    g_twI2 [24*33];        // inv X/Y: (-s, c) packed

// ---------------- f32x2 packed helpers ----------------
__device__ __forceinline__ u64 pk2(float lo, float hi){
    u64 r; asm("mov.b64 %0, {%1,%2};" : "=l"(r) : "f"(lo), "f"(hi)); return r;
}
__device__ __forceinline__ void fma2(u64& d, u64 a, u64 b){
    asm("fma.rn.f32x2 %0, %1, %2, %0;" : "+l"(d) : "l"(a), "l"(b));
}
__device__ __forceinline__ float2 unpk2(u64 v){
    float2 f; asm("mov.b64 {%0,%1}, %2;" : "=f"(f.x), "=f"(f.y) : "l"(v)); return f;
}

// ---------------- init: twiddle tables ----------------
__global__ void k_init() {
    int idx = blockIdx.x * blockDim.x + threadIdx.x;
    if (idx < 384) {
        int k = idx >> 5, t = idx & 31;
        float s, c;
        sincospif((float)((k * t) & 63) / 32.0f, &s, &c);
        g_twTpk[idx] = pk2(c, -s);
        g_twTi2[idx] = (k == 0) ? make_float2(N3INV, 0.0f)
                                : make_float2(2.0f*c*N3INV, -2.0f*s*N3INV);
    } else if (idx < 384 + 792) {
        int r = idx - 384;
        int j = r / 33, u = r % 33;
        int uu = (u < 32) ? u : 0;       // init padding too (unused)
        int f = (j < 12) ? j : j + 40;   // freqs 0..11, 52..63
        float s, c;
        sincospif((float)((f * uu) & 63) / 32.0f, &s, &c);
        g_twXY[r] = make_float2(c, s);
        g_twI1[r] = pk2(c, s);
        g_twI2[r] = pk2(-s, c);
    }
}

// ---------------- repack: register transpose (verified R3) ----------------
__global__ void __launch_bounds__(256) k_repack2(const float* __restrict__ w1, const float* __restrict__ w2,
                                                 const float* __restrict__ w3, const float* __restrict__ w4) {
    int jx = blockIdx.x / 12, jy = blockIdx.x % 12;
    int tid = threadIdx.x;
#pragma unroll
    for (int q = 0; q < 4; q++) {
        const float* w = (q == 0) ? w1 : (q == 1) ? w2 : (q == 2) ? w3 : w4;
        const float4* src = (const float4*)(w + ((size_t)tid*1728 + (jx*12 + jy)*12)*2);
        float2 r[12];
#pragma unroll
        for (int j = 0; j < 6; j++) {
            float4 v = src[j];
            r[2*j]   = make_float2(v.x, v.y);
            r[2*j+1] = make_float2(v.z, v.w);
        }
        int kxi = jx + ((q & 1) ? 12 : 0);
        int kyi = jy + ((q & 2) ? 12 : 0);
        float2* dst = g_W + ((size_t)(kxi*24 + kyi)*12)*256 + tid;
#pragma unroll
        for (int j = 0; j < 12; j++) dst[j*256] = r[j];
    }
}

// ---------------- K1: real DFT over T (radix-2 in-loop, packed) ----------------
// block = 2 slabs; 128 threads; thread = (slab, y), owns all 12 kz
__global__ void __launch_bounds__(128) k_dft_t(const float* __restrict__ x) {
    __shared__ float sx[2*64*65];
    __shared__ u64 stw[384];
    int slab0 = blockIdx.x * 2;
    const float4* xs = (const float4*)(x + (size_t)slab0 * 4096);
    for (int i = threadIdx.x; i < 2048; i += 128) {
        float4 v = xs[i];
        int sl = i >> 10, r = i & 1023;
        int yy = r >> 4, t4 = (r & 15) * 4;
        float* row = &sx[sl*4160 + yy*65 + t4];
        row[0] = v.x; row[1] = v.y; row[2] = v.z; row[3] = v.w;
    }
    for (int i = threadIdx.x; i < 384; i += 128) stw[i] = g_twTpk[i];
    __syncthreads();

    int sl = threadIdx.x >> 6, yy = threadIdx.x & 63;
    const float* row = &sx[sl*4160 + yy*65];
    u64 acc[12];
#pragma unroll
    for (int k = 0; k < 12; k++) acc[k] = 0ull;
#pragma unroll 4
    for (int t1 = 0; t1 < 32; t1++) {
        float a = row[t1], b = row[t1 + 32];
        float E = a + b, O = a - b;
        u64 pE = pk2(E, E), pO = pk2(O, O);
#pragma unroll
        for (int k = 0; k < 12; k++) fma2(acc[k], stw[k*32 + t1], (k & 1) ? pO : pE);
    }
    float2* dst = g_A + (size_t)(slab0 + sl)*768 + yy*12;
#pragma unroll
    for (int k = 0; k < 12; k++) dst[k] = unpk2(acc[k]);
}

// ---------------- K2: complex DFT over Y (radix-2, 3ky x 3kz tile, packed) ----------------
// block = 4 slabs; 128 threads (32/slab); single float2 twiddle table (32 KB smem)
__global__ void __launch_bounds__(128) k_dft_y() {
    __shared__ float2 sEO[4*804];        // [slab][p*396 + k*33 + y1]
    __shared__ float2 stw[792];
    int slab0 = blockIdx.x * 4;
    for (int i = threadIdx.x; i < 1536; i += 128) {
        int sl = i / 384, r = i % 384;   // r = y1*12 + k
        float2 a = g_A[(size_t)(slab0 + sl)*768 + r];
        float2 b = g_A[(size_t)(slab0 + sl)*768 + 384 + r];
        int k = r % 12, y1 = r / 12;
        sEO[sl*804 + k*33 + y1]       = make_float2(a.x + b.x, a.y + b.y);
        sEO[sl*804 + 396 + k*33 + y1] = make_float2(a.x - b.x, a.y - b.y);
    }
    for (int i = threadIdx.x; i < 792; i += 128) stw[i] = g_twXY[i];
    __syncthreads();

    int u = threadIdx.x & 31, sl = threadIdx.x >> 5;
    int q = u & 3, h = u >> 2;
    int p = h & 1, g4 = h >> 1;
    int k0 = q * 3;
    int ky0 = p + 6 * g4;                // ky = ky0 + 2j, j<3 (same parity p)
    const float2* dat = sEO + sl*804 + p*396 + k0*33;
    u64 acc[3][3];
#pragma unroll
    for (int j = 0; j < 3; j++)
#pragma unroll
        for (int z = 0; z < 3; z++) acc[j][z] = 0ull;

#pragma unroll 4
    for (int y1 = 0; y1 < 32; y1++) {
        u64 d1[3], d2[3];
#pragma unroll
        for (int z = 0; z < 3; z++) {
            float2 v = dat[z*33 + y1];
            d1[z] = pk2(v.x, v.y);
            d2[z] = pk2(v.y, -v.x);
        }
#pragma unroll
        for (int j = 0; j < 3; j++) {
            int ky = ky0 + 2*j;
            float2 w = stw[ky*33 + y1];
            u64 cp = pk2(w.x, w.x), sp = pk2(w.y, w.y);
#pragma unroll
            for (int z = 0; z < 3; z++) { fma2(acc[j][z], cp, d1[z]); fma2(acc[j][z], sp, d2[z]); }
        }
    }
    float2* dst = g_Bf + (size_t)(slab0 + sl)*288;
#pragma unroll
    for (int j = 0; j < 3; j++) {
        int ky = ky0 + 2*j;
#pragma unroll
        for (int z = 0; z < 3; z++) dst[ky*12 + k0 + z] = unpk2(acc[j][z]);
    }
}

// ---------------- KB: X-DFT (radix-2, 64->24) + spectral 16x16 mix (R3 shape) ----------------
// block = (b, ky, kz); 384 threads
__global__ void __launch_bounds__(384) kB() {
    __shared__ float2 sIn[16*65];
    __shared__ float2 sAcc[24*16];
    __shared__ float2 stX[792];
    int blk = blockIdx.x;
    int b = blk / 288, r = blk % 288;
    int ky = r / 12, kz = r % 12;
    int tid = threadIdx.x;

    for (int i = tid; i < 1024; i += 384) {
        int c = i >> 6, xx = i & 63;
        sIn[c*65 + xx] = g_Bf[(size_t)((b*16 + c)*64 + xx)*288 + ky*12 + kz];
    }
    for (int i = tid; i < 792; i += 384) stX[i] = g_twXY[i];
    __syncthreads();

    for (int i = tid; i < 512; i += 384) {
        int c = i >> 5, x1 = i & 31;
        float2 a = sIn[c*65 + x1], bb = sIn[c*65 + x1 + 32];
        sIn[c*65 + x1]      = make_float2(a.x + bb.x, a.y + bb.y);
        sIn[c*65 + x1 + 32] = make_float2(a.x - bb.x, a.y - bb.y);
    }
    __syncthreads();

    {   // stage 1: X DFT -> sAcc[kx][c]
        int kx = tid >> 4, c = tid & 15;
        const float2* rowp = &sIn[c*65 + (kx & 1)*32];
        const float2* tw = &stX[kx*33];
        float2 acc = make_float2(0.f, 0.f);
#pragma unroll 4
        for (int x1 = 0; x1 < 32; x1++) {
            float2 w = tw[x1]; float2 v = rowp[x1];
            acc.x += v.x*w.x + v.y*w.y;
            acc.y += v.y*w.x - v.x*w.y;
        }
        sAcc[kx*16 + c] = acc;
    }
    __syncthreads();
    {   // stage 2: per-mode complex channel mix
        int kx = tid >> 4, o = tid & 15;
        const float2* Wp = g_W + ((size_t)((kx*24 + ky)*12 + kz)) * 256;
        float2 acc = make_float2(0.f, 0.f);
#pragma unroll
        for (int i = 0; i < 16; i++) {
            float2 av = sAcc[kx*16 + i];
            float2 w  = Wp[i*16 + o];
            acc.x += av.x*w.x - av.y*w.y;
            acc.y += av.x*w.y + av.y*w.x;
        }
        g_D[(((size_t)(b*16 + o)*24 + ky)*24 + kx)*12 + kz] = acc;
    }
}

// ---------------- KC: inverse X DFT (24 -> 64), parity, 2kz tile, packed ----------------
// block = 2 units (bo,ky) x 192 threads; thread = (x1, kz-pair)
__global__ void __launch_bounds__(384) kC() {
    __shared__ float2 sD[2*292];
    __shared__ u64 sT1[792], sT2[792];
    int unit0 = blockIdx.x * 2;          // unit = bo*24 + ky
    int tid = threadIdx.x;
    for (int i = tid; i < 576; i += 384) {
        int un = i / 288, r = i % 288;
        sD[un*292 + r] = g_D[(size_t)(unit0 + un)*288 + r];
    }
    for (int i = tid; i < 792; i += 384) { sT1[i] = g_twI1[i]; sT2[i] = g_twI2[i]; }
    __syncthreads();

    int un = tid / 192, v = tid % 192;
    int x1 = v & 31, q = v >> 5, k0 = q * 2;
    const float2* D = sD + un*292;
    u64 Se[2], So[2];
    Se[0] = Se[1] = So[0] = So[1] = 0ull;

#pragma unroll 4
    for (int kx = 0; kx < 24; kx++) {
        float2 d0 = D[kx*12 + k0];
        float2 d1 = D[kx*12 + k0 + 1];
        u64 t1 = sT1[kx*33 + x1], t2 = sT2[kx*33 + x1];
        u64* tgt = (kx & 1) ? So : Se;
        fma2(tgt[0], t1, pk2(d0.x, d0.x)); fma2(tgt[0], t2, pk2(d0.y, d0.y));
        fma2(tgt[1], t1, pk2(d1.x, d1.x)); fma2(tgt[1], t2, pk2(d1.y, d1.y));
    }
    float2 se0 = unpk2(Se[0]), so0 = unpk2(So[0]);
    float2 se1 = unpk2(Se[1]), so1 = unpk2(So[1]);
    float4* base = (float4*)(g_Bf + (size_t)(unit0 + un)*768);  // [(bo*24+ky)*64+x][kz]
    base[(x1*12 + k0) >> 1]        = make_float4(se0.x + so0.x, se0.y + so0.y,
                                                se1.x + so1.x, se1.y + so1.y);
    base[((x1 + 32)*12 + k0) >> 1] = make_float4(se0.x - so0.x, se0.y - so0.y,
                                                se1.x - so1.x, se1.y - so1.y);
}

// ---------------- KYI: inverse Y DFT (24 -> 64), parity, 2kz tile, packed ----------------
// block = 2 units (bo,xx) x 192 threads; thread = (y1, kz-pair)
__global__ void __launch_bounds__(384) k_idft_y2() {
    __shared__ float2 sE[2*292];
    __shared__ u64 sT1[792], sT2[792];
    int unit0 = blockIdx.x * 2;          // unit = bo*64 + xx
    int tid = threadIdx.x;
    for (int i = tid; i < 576; i += 384) {
        int un = i / 288, r = i % 288;   // r = ky*12 + kz
        int u2 = unit0 + un;
        int bo = u2 >> 6, xx = u2 & 63;
        int ky = r / 12, kz = r % 12;
        sE[un*292 + r] = g_Bf[((size_t)(bo*24 + ky)*64 + xx)*12 + kz];
    }
    for (int i = tid; i < 792; i += 384) { sT1[i] = g_twI1[i]; sT2[i] = g_twI2[i]; }
    __syncthreads();

    int un = tid / 192, v = tid % 192;
    int y1 = v & 31, q = v >> 5, k0 = q * 2;
    const float2* E = sE + un*292;
    u64 Se[2], So[2];
    Se[0] = Se[1] = So[0] = So[1] = 0ull;

#pragma unroll 4
    for (int ky = 0; ky < 24; ky++) {
        float2 d0 = E[ky*12 + k0];
        float2 d1 = E[ky*12 + k0 + 1];
        u64 t1 = sT1[ky*33 + y1], t2 = sT2[ky*33 + y1];
        u64* tgt = (ky & 1) ? So : Se;
        fma2(tgt[0], t1, pk2(d0.x, d0.x)); fma2(tgt[0], t2, pk2(d0.y, d0.y));
        fma2(tgt[1], t1, pk2(d1.x, d1.x)); fma2(tgt[1], t2, pk2(d1.y, d1.y));
    }
    float2 se0 = unpk2(Se[0]), so0 = unpk2(So[0]);
    float2 se1 = unpk2(Se[1]), so1 = unpk2(So[1]);
    float4* base = (float4*)(g_A + (size_t)(unit0 + un)*768);   // [slab][y*12+k]
    base[(y1*12 + k0) >> 1]        = make_float4(se0.x + so0.x, se0.y + so0.y,
                                                se1.x + so1.x, se1.y + so1.y);
    base[((y1 + 32)*12 + k0) >> 1] = make_float4(se0.x - so0.x, se0.y - so0.y,
                                                se1.x - so1.x, se1.y - so1.y);
}

// ---------------- K7: inverse rfft over T (parity, packed halves) + ReLU + packed mix ----------------
// block = (b, x, y-group-of-8); 256 threads; warp per y-line; lane owns t and t+32
__global__ void __launch_bounds__(256) k_ifft_t_mix(const float* __restrict__ lo_w,
                                                    const float* __restrict__ lo_b,
                                                    float* __restrict__ out) {
    __shared__ u64 sF[8*192];            // [slab][c*12+k] packed (re,im)
    __shared__ u64 sTi[384];             // packed (A,B)
    __shared__ u64 sWq[256];
    __shared__ float sB[16];
    int blk = blockIdx.x;
    int b   = blk >> 9;
    int rr  = blk & 511;
    int xx  = rr >> 3;
    int yy0 = (rr & 7) * 8;

    for (int i = threadIdx.x; i < 1536; i += 256) {
        int sl = i / 192, r2 = i % 192;
        int c = r2 / 12, k = r2 % 12;
        sF[i] = ((const u64*)g_A)[(((size_t)(b*16 + c)*64 + xx)*64 + yy0 + sl)*12 + k];
    }
    for (int i = threadIdx.x; i < 384; i += 256) sTi[i] = ((const u64*)g_twTi2)[i];
    if (threadIdx.x < 256) { float w = lo_w[threadIdx.x]; sWq[threadIdx.x] = pk2(w, w); }
    if (threadIdx.x < 16)  sB[threadIdx.x] = lo_b[threadIdx.x];
    __syncthreads();

    int w    = threadIdx.x >> 5;
    int lane = threadIdx.x & 31;
    int yy   = yy0 + w;
    const u64* F = &sF[w*192];

    u64 p[16];
#pragma unroll
    for (int half = 0; half < 2; half++) {
        u64 aE[8], aO[8];
#pragma unroll
        for (int c8 = 0; c8 < 8; c8++) { aE[c8] = 0ull; aO[c8] = 0ull; }
#pragma unroll
        for (int k = 0; k < 12; k++) {
            u64 ti = sTi[k*32 + lane];
            const u64* Fc = F + (half*8)*12 + k;
#pragma unroll
            for (int c8 = 0; c8 < 8; c8++) {
                if (k & 1) fma2(aO[c8], Fc[c8*12], ti);
                else       fma2(aE[c8], Fc[c8*12], ti);
            }
        }
#pragma unroll
        for (int c8 = 0; c8 < 8; c8++) {
            float2 e = unpk2(aE[c8]), o = unpk2(aO[c8]);
            float Ev = e.x + e.y, Ov = o.x + o.y;
            p[half*8 + c8] = pk2(fmaxf(Ev + Ov, 0.f), fmaxf(Ev - Ov, 0.f));
        }
    }
#pragma unroll
    for (int o = 0; o < 16; o++) {
        u64 acc = pk2(sB[o], sB[o]);
#pragma unroll
        for (int c = 0; c < 16; c++) fma2(acc, sWq[o*16 + c], p[c]);
        float2 rv = unpk2(acc);
        float* dst = out + ((((size_t)(b*16 + o)*64 + xx)*64 + yy)*64);
        dst[lane]      = rv.x;
        dst[lane + 32] = rv.y;
    }
}

// ---------------- launch ----------------
extern "C" void kernel_launch(void* const* d_in, const int* in_sizes, int n_in,
                              void* d_out, int out_size) {
    const float* x    = (const float*)d_in[0];
    const float* w1   = (const float*)d_in[1];
    const float* w2   = (const float*)d_in[2];
    const float* w3   = (const float*)d_in[3];
    const float* w4   = (const float*)d_in[4];
    const float* lo_w = (const float*)d_in[5];
    const float* lo_b = (const float*)d_in[6];
    float* out = (float*)d_out;

    k_init<<<5, 256>>>();
    k_repack2<<<144, 256>>>(w1, w2, w3, w4);
    k_dft_t<<<4096, 128>>>(x);                       // T 64->12 (radix-2, packed)
    k_dft_y<<<2048, 128>>>();                        // Y 64->24 (3x3 tile, packed, 32KB smem)
    kB<<<2304, 384>>>();                             // X 64->24 + channel mix (R3 shape)
    kC<<<1536, 384>>>();                             // X 24->64 (parity, 2kz tile, packed)
    k_idft_y2<<<4096, 384>>>();                      // Y 24->64 (parity, 2kz tile, packed)
    k_ifft_t_mix<<<4096, 256>>>(lo_w, lo_b, out);    // T 12->64 + relu + 1x1 (packed halves)
}

// round 6
// speedup vs baseline: 1.4257x; 1.0921x over previous
#include <cuda_runtime.h>
#include <math.h>

#define N3INV (1.0f/262144.0f)
typedef unsigned long long u64;

// ---------------- scratch (static device memory; no allocations) ----------------
__device__ float2 g_Bf[8*16*64*24*12];   // 19 MB: fwd Y out [slab][ky*12+kz]; inv-X out [(bo*24+ky)*64+x][kz]
__device__ float2 g_D [8*16*24*24*12];   //  7 MB: modes [((bo)*24+ky)*24+kx][kz]
__device__ float2 g_W [24*24*12*16*16];  // 14 MB: repacked weights, mode-major
__device__ u64    g_twTpk[12*32];        // fwd T: (c, -s) packed
__device__ float2 g_twTi2[12*32];        // inv T: (A, B) = (2c/N^3, -2s/N^3); k=0: (1/N^3, 0)
__device__ float2 g_twXY [24*33];        // fwd X/Y: (c, s)  [padded stride 33]
__device__ u64    g_twI1 [24*33];        // inv X/Y: (c, s) packed
__device__ u64    g_twI2 [24*33];        // inv X/Y: (-s, c) packed

// ---------------- f32x2 packed helpers ----------------
__device__ __forceinline__ u64 pk2(float lo, float hi){
    u64 r; asm("mov.b64 %0, {%1,%2};" : "=l"(r) : "f"(lo), "f"(hi)); return r;
}
__device__ __forceinline__ void fma2(u64& d, u64 a, u64 b){
    asm("fma.rn.f32x2 %0, %1, %2, %0;" : "+l"(d) : "l"(a), "l"(b));
}
__device__ __forceinline__ float2 unpk2(u64 v){
    float2 f; asm("mov.b64 {%0,%1}, %2;" : "=f"(f.x), "=f"(f.y) : "l"(v)); return f;
}

// ---------------- init: twiddle tables ----------------
__global__ void k_init() {
    int idx = blockIdx.x * blockDim.x + threadIdx.x;
    if (idx < 384) {
        int k = idx >> 5, t = idx & 31;
        float s, c;
        sincospif((float)((k * t) & 63) / 32.0f, &s, &c);
        g_twTpk[idx] = pk2(c, -s);
        g_twTi2[idx] = (k == 0) ? make_float2(N3INV, 0.0f)
                                : make_float2(2.0f*c*N3INV, -2.0f*s*N3INV);
    } else if (idx < 384 + 792) {
        int r = idx - 384;
        int j = r / 33, u = r % 33;
        int uu = (u < 32) ? u : 0;       // init padding too (unused)
        int f = (j < 12) ? j : j + 40;   // freqs 0..11, 52..63
        float s, c;
        sincospif((float)((f * uu) & 63) / 32.0f, &s, &c);
        g_twXY[r] = make_float2(c, s);
        g_twI1[r] = pk2(c, s);
        g_twI2[r] = pk2(-s, c);
    }
}

// ---------------- repack: register transpose (verified R3) ----------------
__global__ void __launch_bounds__(256) k_repack2(const float* __restrict__ w1, const float* __restrict__ w2,
                                                 const float* __restrict__ w3, const float* __restrict__ w4) {
    int jx = blockIdx.x / 12, jy = blockIdx.x % 12;
    int tid = threadIdx.x;
#pragma unroll
    for (int q = 0; q < 4; q++) {
        const float* w = (q == 0) ? w1 : (q == 1) ? w2 : (q == 2) ? w3 : w4;
        const float4* src = (const float4*)(w + ((size_t)tid*1728 + (jx*12 + jy)*12)*2);
        float2 r[12];
#pragma unroll
        for (int j = 0; j < 6; j++) {
            float4 v = src[j];
            r[2*j]   = make_float2(v.x, v.y);
            r[2*j+1] = make_float2(v.z, v.w);
        }
        int kxi = jx + ((q & 1) ? 12 : 0);
        int kyi = jy + ((q & 2) ? 12 : 0);
        float2* dst = g_W + ((size_t)(kxi*24 + kyi)*12)*256 + tid;
#pragma unroll
        for (int j = 0; j < 12; j++) dst[j*256] = r[j];
    }
}

// ---------------- kA2: fused T-DFT (radix-2) + Y-DFT (radix-2) ----------------
// block = 2 slabs of (b,c,x); 256 threads; dynamic smem 54 KB -> 4 blocks/SM
// smem plan (u64-aligned):
//   sx  : float [2*4160]   input tiles [y][t] pad 65; reused (as float2) for EO-over-y buffer
//   sA  : float2[2*792]    raw T-DFT output [sl][k*66 + y]
//   stT : u64   [384]      fwd T twiddles (c,-s)
//   stY : float2[792]      fwd Y twiddles (c,s) pad 33
#define KA2_SMEM (2*4160*4 + 2*792*8 + 384*8 + 792*8)
__global__ void __launch_bounds__(256, 4) kA2(const float* __restrict__ x) {
    extern __shared__ char smraw[];
    float*  sx  = (float*)smraw;
    float2* sA  = (float2*)(smraw + 2*4160*4);
    u64*    stT = (u64*)(smraw + 2*4160*4 + 2*792*8);
    float2* stY = (float2*)(smraw + 2*4160*4 + 2*792*8 + 384*8);
    float2* sEO = (float2*)sx;           // reused after T-phase: [sl*804 + p*396 + k*33 + y1]

    int slab0 = blockIdx.x * 2;
    int tid = threadIdx.x;

    const float4* xs = (const float4*)(x + (size_t)slab0 * 4096);
    for (int i = tid; i < 2048; i += 256) {
        float4 v = xs[i];
        int sl = i >> 10, r = i & 1023;
        int yy = r >> 4, t4 = (r & 15) * 4;
        float* row = &sx[sl*4160 + yy*65 + t4];
        row[0] = v.x; row[1] = v.y; row[2] = v.z; row[3] = v.w;
    }
    for (int i = tid; i < 384; i += 256) stT[i] = g_twTpk[i];
    for (int i = tid; i < 792; i += 256) stY[i] = g_twXY[i];
    __syncthreads();

    // ---- phase T: radix-2 in-loop, thread = (sl, yy, khalf), 6 kz each ----
    {
        int sl = tid >> 7, g = (tid >> 6) & 1, yy = tid & 63;
        int kb = g * 6;
        const float* row = &sx[sl*4160 + yy*65];
        u64 acc[6];
#pragma unroll
        for (int j = 0; j < 6; j++) acc[j] = 0ull;
#pragma unroll 4
        for (int t1 = 0; t1 < 32; t1++) {
            float a = row[t1], b = row[t1 + 32];
            float E = a + b, O = a - b;
            u64 pE = pk2(E, E), pO = pk2(O, O);
#pragma unroll
            for (int j = 0; j < 6; j++) {
                int k = kb + j;
                fma2(acc[j], stT[k*32 + t1], (k & 1) ? pO : pE);
            }
        }
        float2* dst = sA + sl*792 + yy;
#pragma unroll
        for (int j = 0; j < 6; j++) dst[(kb + j)*66] = unpk2(acc[j]);
    }
    __syncthreads();

    // ---- phase EO over y: sA raw -> sEO (in sx region) ----
    for (int i = tid; i < 768; i += 256) {
        int sl = i >> 9 ? 1 : (i >= 384);         // sl = i/384
        int r  = i - sl*384;                      // r = k*32 + y1
        int k = r >> 5, y1 = r & 31;
        float2 a = sA[sl*792 + k*66 + y1];
        float2 b = sA[sl*792 + k*66 + 32 + y1];
        sEO[sl*804 + k*33 + y1]       = make_float2(a.x + b.x, a.y + b.y);
        sEO[sl*804 + 396 + k*33 + y1] = make_float2(a.x - b.x, a.y - b.y);
    }
    __syncthreads();

    // ---- phase Y: 96 threads/slab: (ky, kz-triple) ----
    if (tid < 192) {
        int sl = tid / 96, v = tid % 96;
        int ky = v >> 2, q = v & 3, k0 = q * 3;
        int p = ky & 1;
        const float2* dat = sEO + sl*804 + p*396 + k0*33;
        const float2* tw  = stY + ky*33;
        u64 acc[3];
        acc[0] = acc[1] = acc[2] = 0ull;
#pragma unroll 4
        for (int y1 = 0; y1 < 32; y1++) {
            float2 w = tw[y1];
            u64 cp = pk2(w.x, w.x), sp = pk2(w.y, w.y);
#pragma unroll
            for (int z = 0; z < 3; z++) {
                float2 vv = dat[z*33 + y1];
                fma2(acc[z], cp, pk2(vv.x, vv.y));    // (re,im) * c
                fma2(acc[z], sp, pk2(vv.y, -vv.x));   // + (im,-re) * s  => e^{-i th}
            }
        }
        float2* dst = g_Bf + (size_t)(slab0 + sl)*288 + ky*12 + k0;
#pragma unroll
        for (int z = 0; z < 3; z++) dst[z] = unpk2(acc[z]);
    }
}

// ---------------- kB: X-DFT (radix-2, 64->24) + spectral 16x16 mix (R3/R5 shape) ----------------
__global__ void __launch_bounds__(384) kB() {
    __shared__ float2 sIn[16*65];
    __shared__ float2 sAcc[24*16];
    __shared__ float2 stX[792];
    int blk = blockIdx.x;
    int b = blk / 288, r = blk % 288;
    int ky = r / 12, kz = r % 12;
    int tid = threadIdx.x;

    for (int i = tid; i < 1024; i += 384) {
        int c = i >> 6, xx = i & 63;
        sIn[c*65 + xx] = g_Bf[(size_t)((b*16 + c)*64 + xx)*288 + ky*12 + kz];
    }
    for (int i = tid; i < 792; i += 384) stX[i] = g_twXY[i];
    __syncthreads();

    for (int i = tid; i < 512; i += 384) {
        int c = i >> 5, x1 = i & 31;
        float2 a = sIn[c*65 + x1], bb = sIn[c*65 + x1 + 32];
        sIn[c*65 + x1]      = make_float2(a.x + bb.x, a.y + bb.y);
        sIn[c*65 + x1 + 32] = make_float2(a.x - bb.x, a.y - bb.y);
    }
    __syncthreads();

    {   // stage 1: X DFT -> sAcc[kx][c]
        int kx = tid >> 4, c = tid & 15;
        const float2* rowp = &sIn[c*65 + (kx & 1)*32];
        const float2* tw = &stX[kx*33];
        float2 acc = make_float2(0.f, 0.f);
#pragma unroll 4
        for (int x1 = 0; x1 < 32; x1++) {
            float2 w = tw[x1]; float2 v = rowp[x1];
            acc.x += v.x*w.x + v.y*w.y;
            acc.y += v.y*w.x - v.x*w.y;
        }
        sAcc[kx*16 + c] = acc;
    }
    __syncthreads();
    {   // stage 2: per-mode complex channel mix
        int kx = tid >> 4, o = tid & 15;
        const float2* Wp = g_W + ((size_t)((kx*24 + ky)*12 + kz)) * 256;
        float2 acc = make_float2(0.f, 0.f);
#pragma unroll
        for (int i = 0; i < 16; i++) {
            float2 av = sAcc[kx*16 + i];
            float2 w  = Wp[i*16 + o];
            acc.x += av.x*w.x - av.y*w.y;
            acc.y += av.x*w.y + av.y*w.x;
        }
        g_D[(((size_t)(b*16 + o)*24 + ky)*24 + kx)*12 + kz] = acc;
    }
}

// ---------------- kC: inverse X DFT (24 -> 64), parity, 2kz tile, packed (R5) ----------------
__global__ void __launch_bounds__(384) kC() {
    __shared__ float2 sD[2*292];
    __shared__ u64 sT1[792], sT2[792];
    int unit0 = blockIdx.x * 2;          // unit = bo*24 + ky
    int tid = threadIdx.x;
    for (int i = tid; i < 576; i += 384) {
        int un = i / 288, r = i % 288;
        sD[un*292 + r] = g_D[(size_t)(unit0 + un)*288 + r];
    }
    for (int i = tid; i < 792; i += 384) { sT1[i] = g_twI1[i]; sT2[i] = g_twI2[i]; }
    __syncthreads();

    int un = tid / 192, v = tid % 192;
    int x1 = v & 31, q = v >> 5, k0 = q * 2;
    const float2* D = sD + un*292;
    u64 Se[2], So[2];
    Se[0] = Se[1] = So[0] = So[1] = 0ull;

#pragma unroll 4
    for (int kx = 0; kx < 24; kx++) {
        float2 d0 = D[kx*12 + k0];
        float2 d1 = D[kx*12 + k0 + 1];
        u64 t1 = sT1[kx*33 + x1], t2 = sT2[kx*33 + x1];
        u64* tgt = (kx & 1) ? So : Se;
        fma2(tgt[0], t1, pk2(d0.x, d0.x)); fma2(tgt[0], t2, pk2(d0.y, d0.y));
        fma2(tgt[1], t1, pk2(d1.x, d1.x)); fma2(tgt[1], t2, pk2(d1.y, d1.y));
    }
    float2 se0 = unpk2(Se[0]), so0 = unpk2(So[0]);
    float2 se1 = unpk2(Se[1]), so1 = unpk2(So[1]);
    float4* base = (float4*)(g_Bf + (size_t)(unit0 + un)*768);  // [(bo*24+ky)*64+x][kz]
    base[(x1*12 + k0) >> 1]        = make_float4(se0.x + so0.x, se0.y + so0.y,
                                                se1.x + so1.x, se1.y + so1.y);
    base[((x1 + 32)*12 + k0) >> 1] = make_float4(se0.x - so0.x, se0.y - so0.y,
                                                se1.x - so1.x, se1.y - so1.y);
}

// ---------------- kD2: fused inv-Y + inv-T + ReLU + 16x16 mix + bias ----------------
// block = (b, xx); 512 threads; y in 4 chunks of 16 lines; 107 KB dyn smem -> 2 blocks/SM
// smem (u64 units): sE1[4608] (re,re), sE2[4608] (im,im), sF[3072] packed lines,
//                   sT1[792], sTi[384], sWq[256], sB[16 floats]
#define KD2_SMEM ((4608 + 4608 + 3072 + 792 + 384 + 256)*8 + 64)
__global__ void __launch_bounds__(512, 2) kD2(const float* __restrict__ lo_w,
                                              const float* __restrict__ lo_b,
                                              float* __restrict__ out) {
    extern __shared__ u64 sm[];
    u64* sE1 = sm;                 // [c*288 + ky*12 + kz] = (re,re)
    u64* sE2 = sE1 + 4608;         //                      = (im,im)
    u64* sF  = sE2 + 4608;         // [(c*16 + line)*12 + k] packed (re,im)
    u64* sT1 = sF + 3072;          // (c,s) inv twiddles, pad 33
    u64* sTi = sT1 + 792;          // inv-T (A,B)
    u64* sWq = sTi + 384;          // lo_w dup-packed
    float* sB = (float*)(sWq + 256);

    int tid = threadIdx.x;
    int b = blockIdx.x >> 6, xx = blockIdx.x & 63;

    for (int i = tid; i < 4608; i += 512) {
        int c = i / 288, r = i % 288;              // r = ky*12 + kz
        int ky = r / 12, kz = r % 12;
        float2 d = g_Bf[((size_t)((b*16 + c)*24 + ky)*64 + xx)*12 + kz];
        sE1[i] = pk2(d.x, d.x);
        sE2[i] = pk2(d.y, d.y);
    }
    for (int i = tid; i < 792; i += 512) sT1[i] = g_twI1[i];
    for (int i = tid; i < 384; i += 512) sTi[i] = ((const u64*)g_twTi2)[i];
    if (tid < 256) { float w = lo_w[tid]; sWq[tid] = pk2(w, w); }
    if (tid < 16)  sB[tid] = lo_b[tid];
    __syncthreads();

    int c  = tid >> 5;                 // phase-1 channel (warp-uniform)
    int l  = (tid >> 2) & 7;           // phase-1 y1 local
    int q  = tid & 3;                  // phase-1 kz triple
    int k0 = q * 3;
    int w    = tid >> 5;               // phase-2 warp = line
    int lane = tid & 31;

    for (int a = 0; a < 4; a++) {
        // ---- phase 1: inverse Y (parity), write 16 lines into sF ----
        {
            int y1 = 8*a + l;
            const u64* E1 = sE1 + c*288;
            const u64* E2 = sE2 + c*288;
            u64 Se[3], So[3];
            Se[0]=Se[1]=Se[2]=0ull; So[0]=So[1]=So[2]=0ull;
#pragma unroll 4
            for (int ky = 0; ky < 24; ky++) {
                u64 t1 = sT1[ky*33 + y1];
                float2 f = unpk2(t1);
                u64 t2 = pk2(-f.y, f.x);
                u64* tgt = (ky & 1) ? So : Se;
                const u64* e1 = E1 + ky*12 + k0;
                const u64* e2 = E2 + ky*12 + k0;
#pragma unroll
                for (int z = 0; z < 3; z++) { fma2(tgt[z], t1, e1[z]); fma2(tgt[z], t2, e2[z]); }
            }
#pragma unroll
            for (int z = 0; z < 3; z++) {
                float2 se = unpk2(Se[z]), so = unpk2(So[z]);
                sF[(c*16 + l)*12 + k0 + z]     = pk2(se.x + so.x, se.y + so.y);
                sF[(c*16 + l + 8)*12 + k0 + z] = pk2(se.x - so.x, se.y - so.y);
            }
        }
        __syncthreads();

        // ---- phase 2: inverse T (parity) + ReLU + packed 1x1 mix; warp = line ----
        {
            int y = 8*a + (w & 7) + ((w & 8) ? 32 : 0);
            u64 p[16];
#pragma unroll
            for (int qt = 0; qt < 4; qt++) {
                u64 aE[4], aO[4];
                aE[0]=aE[1]=aE[2]=aE[3]=0ull;
                aO[0]=aO[1]=aO[2]=aO[3]=0ull;
#pragma unroll
                for (int k = 0; k < 12; k++) {
                    u64 ti = sTi[k*32 + lane];
#pragma unroll
                    for (int c4 = 0; c4 < 4; c4++) {
                        u64 f = sF[((qt*4 + c4)*16 + w)*12 + k];   // warp-uniform broadcast
                        if (k & 1) fma2(aO[c4], f, ti);
                        else       fma2(aE[c4], f, ti);
                    }
                }
#pragma unroll
                for (int c4 = 0; c4 < 4; c4++) {
                    float2 e = unpk2(aE[c4]), o = unpk2(aO[c4]);
                    float Ev = e.x + e.y, Ov = o.x + o.y;
                    p[qt*4 + c4] = pk2(fmaxf(Ev + Ov, 0.f), fmaxf(Ev - Ov, 0.f));
                }
            }
#pragma unroll
            for (int o = 0; o < 16; o++) {
                u64 acc = pk2(sB[o], sB[o]);
#pragma unroll
                for (int cc = 0; cc < 16; cc++) fma2(acc, sWq[o*16 + cc], p[cc]);
                float2 rv = unpk2(acc);
                float* dst = out + (((size_t)(b*16 + o)*64 + xx)*64 + y)*64;
                dst[lane]      = rv.x;
                dst[lane + 32] = rv.y;
            }
        }
        __syncthreads();
    }
}

// ---------------- launch ----------------
extern "C" void kernel_launch(void* const* d_in, const int* in_sizes, int n_in,
                              void* d_out, int out_size) {
    const float* x    = (const float*)d_in[0];
    const float* w1   = (const float*)d_in[1];
    const float* w2   = (const float*)d_in[2];
    const float* w3   = (const float*)d_in[3];
    const float* w4   = (const float*)d_in[4];
    const float* lo_w = (const float*)d_in[5];
    const float* lo_b = (const float*)d_in[6];
    float* out = (float*)d_out;

    cudaFuncSetAttribute(kA2, cudaFuncAttributeMaxDynamicSharedMemorySize, KA2_SMEM);
    cudaFuncSetAttribute(kD2, cudaFuncAttributeMaxDynamicSharedMemorySize, KD2_SMEM);

    k_init<<<5, 256>>>();
    k_repack2<<<144, 256>>>(w1, w2, w3, w4);
    kA2<<<4096, 256, KA2_SMEM>>>(x);                 // T 64->12 + Y 64->24 fused
    kB<<<2304, 384>>>();                             // X 64->24 + channel mix
    kC<<<1536, 384>>>();                             // X 24->64
    kD2<<<512, 512, KD2_SMEM>>>(lo_w, lo_b, out);    // Y 24->64 + T 12->64 + relu + 1x1 fused
}

// round 7
// speedup vs baseline: 1.4769x; 1.0359x over previous
#include <cuda_runtime.h>
#include <math.h>

#define N3INV (1.0f/262144.0f)
typedef unsigned long long u64;

// ---------------- scratch (static device memory; no allocations) ----------------
__device__ float2 g_Bm[8*24*12*1024];    // 19 MB: fwd Y out, mode-major [((b*24+ky)*12+kz)*1024 + c*64+x]
__device__ float2 g_Bf[8*16*64*24*12];   // 19 MB: inv-X out [(bo*24+ky)*64+x][kz]
__device__ float2 g_D [8*16*24*24*12];   //  7 MB: modes [((bo)*24+ky)*24+kx][kz]
__device__ float2 g_W [24*24*12*16*16];  // 14 MB: repacked weights, mode-major
__device__ u64    g_twTpk[12*32];        // fwd T: (c, -s) packed
__device__ float2 g_twTi2[12*32];        // inv T: (A, B) = (2c/N^3, -2s/N^3); k=0: (1/N^3, 0)
__device__ float2 g_twXY [24*33];        // fwd X/Y: (c, s)  [padded stride 33]
__device__ u64    g_twI1 [24*33];        // inv X/Y: (c, s) packed
__device__ u64    g_twI2 [24*33];        // inv X/Y: (-s, c) packed

// ---------------- f32x2 packed helpers ----------------
__device__ __forceinline__ u64 pk2(float lo, float hi){
    u64 r; asm("mov.b64 %0, {%1,%2};" : "=l"(r) : "f"(lo), "f"(hi)); return r;
}
__device__ __forceinline__ void fma2(u64& d, u64 a, u64 b){
    asm("fma.rn.f32x2 %0, %1, %2, %0;" : "+l"(d) : "l"(a), "l"(b));
}
__device__ __forceinline__ float2 unpk2(u64 v){
    float2 f; asm("mov.b64 {%0,%1}, %2;" : "=f"(f.x), "=f"(f.y) : "l"(v)); return f;
}

// ---------------- init: twiddle tables ----------------
__global__ void k_init() {
    int idx = blockIdx.x * blockDim.x + threadIdx.x;
    if (idx < 384) {
        int k = idx >> 5, t = idx & 31;
        float s, c;
        sincospif((float)((k * t) & 63) / 32.0f, &s, &c);
        g_twTpk[idx] = pk2(c, -s);
        g_twTi2[idx] = (k == 0) ? make_float2(N3INV, 0.0f)
                                : make_float2(2.0f*c*N3INV, -2.0f*s*N3INV);
    } else if (idx < 384 + 792) {
        int r = idx - 384;
        int j = r / 33, u = r % 33;
        int uu = (u < 32) ? u : 0;
        int f = (j < 12) ? j : j + 40;   // freqs 0..11, 52..63
        float s, c;
        sincospif((float)((f * uu) & 63) / 32.0f, &s, &c);
        g_twXY[r] = make_float2(c, s);
        g_twI1[r] = pk2(c, s);
        g_twI2[r] = pk2(-s, c);
    }
}

// ---------------- repack: register transpose (verified R3) ----------------
__global__ void __launch_bounds__(256) k_repack2(const float* __restrict__ w1, const float* __restrict__ w2,
                                                 const float* __restrict__ w3, const float* __restrict__ w4) {
    int jx = blockIdx.x / 12, jy = blockIdx.x % 12;
    int tid = threadIdx.x;
#pragma unroll
    for (int q = 0; q < 4; q++) {
        const float* w = (q == 0) ? w1 : (q == 1) ? w2 : (q == 2) ? w3 : w4;
        const float4* src = (const float4*)(w + ((size_t)tid*1728 + (jx*12 + jy)*12)*2);
        float2 r[12];
#pragma unroll
        for (int j = 0; j < 6; j++) {
            float4 v = src[j];
            r[2*j]   = make_float2(v.x, v.y);
            r[2*j+1] = make_float2(v.z, v.w);
        }
        int kxi = jx + ((q & 1) ? 12 : 0);
        int kyi = jy + ((q & 2) ? 12 : 0);
        float2* dst = g_W + ((size_t)(kxi*24 + kyi)*12)*256 + tid;
#pragma unroll
        for (int j = 0; j < 12; j++) dst[j*256] = r[j];
    }
}

// ---------------- kA2: fused T-DFT (radix-2) + Y-DFT (radix-2) ----------------
// block = 2 slabs of (b,c,x); 256 threads; dynamic smem 54 KB -> 4 blocks/SM
#define KA2_SMEM (2*4160*4 + 2*792*8 + 384*8 + 792*8)
__global__ void __launch_bounds__(256, 4) kA2(const float* __restrict__ x) {
    extern __shared__ char smraw[];
    float*  sx  = (float*)smraw;
    float2* sA  = (float2*)(smraw + 2*4160*4);
    u64*    stT = (u64*)(smraw + 2*4160*4 + 2*792*8);
    float2* stY = (float2*)(smraw + 2*4160*4 + 2*792*8 + 384*8);
    float2* sEO = (float2*)sx;           // reused after T-phase: [sl*804 + p*396 + k*33 + y1]

    int slab0 = blockIdx.x * 2;
    int tid = threadIdx.x;

    const float4* xs = (const float4*)(x + (size_t)slab0 * 4096);
    for (int i = tid; i < 2048; i += 256) {
        float4 v = xs[i];
        int sl = i >> 10, r = i & 1023;
        int yy = r >> 4, t4 = (r & 15) * 4;
        float* row = &sx[sl*4160 + yy*65 + t4];
        row[0] = v.x; row[1] = v.y; row[2] = v.z; row[3] = v.w;
    }
    for (int i = tid; i < 384; i += 256) stT[i] = g_twTpk[i];
    for (int i = tid; i < 792; i += 256) stY[i] = g_twXY[i];
    __syncthreads();

    // ---- phase T: radix-2 in-loop, thread = (sl, yy, khalf), 6 kz each ----
    {
        int sl = tid >> 7, g = (tid >> 6) & 1, yy = tid & 63;
        int kb = g * 6;
        const float* row = &sx[sl*4160 + yy*65];
        u64 acc[6];
#pragma unroll
        for (int j = 0; j < 6; j++) acc[j] = 0ull;
#pragma unroll 4
        for (int t1 = 0; t1 < 32; t1++) {
            float a = row[t1], b = row[t1 + 32];
            float E = a + b, O = a - b;
            u64 pE = pk2(E, E), pO = pk2(O, O);
#pragma unroll
            for (int j = 0; j < 6; j++) {
                int k = kb + j;
                fma2(acc[j], stT[k*32 + t1], (k & 1) ? pO : pE);
            }
        }
        float2* dst = sA + sl*792 + yy;
#pragma unroll
        for (int j = 0; j < 6; j++) dst[(kb + j)*66] = unpk2(acc[j]);
    }
    __syncthreads();

    // ---- phase EO over y: sA raw -> sEO (in sx region) ----
    for (int i = tid; i < 768; i += 256) {
        int sl = (i >= 384);
        int r  = i - sl*384;                      // r = k*32 + y1
        int k = r >> 5, y1 = r & 31;
        float2 a = sA[sl*792 + k*66 + y1];
        float2 b = sA[sl*792 + k*66 + 32 + y1];
        sEO[sl*804 + k*33 + y1]       = make_float2(a.x + b.x, a.y + b.y);
        sEO[sl*804 + 396 + k*33 + y1] = make_float2(a.x - b.x, a.y - b.y);
    }
    __syncthreads();

    // ---- phase Y: 96 threads: (ky, kz-triple), both slabs -> float4 writes ----
    if (tid < 96) {
        int ky = tid >> 2, q = tid & 3, k0 = q * 3;
        int p = ky & 1;
        const float2* tw = stY + ky*33;
        const float2* dat0 = sEO + p*396 + k0*33;
        const float2* dat1 = sEO + 804 + p*396 + k0*33;
        u64 acc0[3], acc1[3];
#pragma unroll
        for (int z = 0; z < 3; z++) { acc0[z] = 0ull; acc1[z] = 0ull; }
#pragma unroll 4
        for (int y1 = 0; y1 < 32; y1++) {
            float2 w = tw[y1];
            u64 cp = pk2(w.x, w.x), sp = pk2(w.y, w.y);
#pragma unroll
            for (int z = 0; z < 3; z++) {
                float2 v0 = dat0[z*33 + y1];
                fma2(acc0[z], cp, pk2(v0.x, v0.y));
                fma2(acc0[z], sp, pk2(v0.y, -v0.x));
                float2 v1 = dat1[z*33 + y1];
                fma2(acc1[z], cp, pk2(v1.x, v1.y));
                fma2(acc1[z], sp, pk2(v1.y, -v1.x));
            }
        }
        int bb = slab0 >> 10, cc = (slab0 >> 6) & 15, xx0 = slab0 & 63;
#pragma unroll
        for (int z = 0; z < 3; z++) {
            float2 r0 = unpk2(acc0[z]), r1 = unpk2(acc1[z]);
            float4* dst = (float4*)(g_Bm + ((size_t)(bb*24 + ky)*12 + k0 + z)*1024 + cc*64 + xx0);
            *dst = make_float4(r0.x, r0.y, r1.x, r1.y);
        }
    }
}

// ---------------- kB: X-DFT (radix-2, 2kz tile, packed) + spectral 16x16 mix ----------------
// block = (b, ky, kz-pair); grid 1152; 384 threads
__global__ void __launch_bounds__(384) kB() {
    __shared__ float2 sIn[16*65*2];      // [(c*65+xx)*2 + kzi]  (float4 view: [c*65+xx])
    __shared__ float2 sAcc[24*16*2];     // [(kx*16+c)*2 + kzi]
    __shared__ float2 stX[792];
    int blk = blockIdx.x;
    int b = blk / 144, r = blk % 144;
    int ky = r / 6, q = r % 6;
    int k0 = q * 2;
    int tid = threadIdx.x;

    const float4* src = (const float4*)(g_Bm + ((size_t)(b*24 + ky)*12 + k0)*1024);
    for (int i = tid; i < 1024; i += 384) {
        int kzi = i >> 9, j = i & 511;
        float4 v = src[kzi*512 + j];
        int c = j >> 5, x2 = (j & 31)*2;
        int base = (c*65 + x2)*2 + kzi;
        sIn[base]     = make_float2(v.x, v.y);
        sIn[base + 2] = make_float2(v.z, v.w);
    }
    for (int i = tid; i < 792; i += 384) stX[i] = g_twXY[i];
    __syncthreads();

    // EO over x (both kz at once via float4)
    float4* sIn4 = (float4*)sIn;
    for (int i = tid; i < 512; i += 384) {
        int c = i >> 5, x1 = i & 31;
        float4 a = sIn4[c*65 + x1], bb4 = sIn4[c*65 + x1 + 32];
        sIn4[c*65 + x1]      = make_float4(a.x + bb4.x, a.y + bb4.y, a.z + bb4.z, a.w + bb4.w);
        sIn4[c*65 + x1 + 32] = make_float4(a.x - bb4.x, a.y - bb4.y, a.z - bb4.z, a.w - bb4.w);
    }
    __syncthreads();

    {   // stage 1: X DFT -> sAcc[kx][c][2kz]
        int kx = tid >> 4, c = tid & 15;
        const float4* rowp = sIn4 + c*65 + (kx & 1)*32;
        const float2* tw = &stX[kx*33];
        u64 acc0 = 0ull, acc1 = 0ull;    // packed (re,im) per kz
#pragma unroll 4
        for (int x1 = 0; x1 < 32; x1++) {
            float4 v = rowp[x1];
            float2 w = tw[x1];
            u64 cp = pk2(w.x, w.x), sp = pk2(w.y, w.y);
            fma2(acc0, cp, pk2(v.x, v.y));  fma2(acc0, sp, pk2(v.y, -v.x));
            fma2(acc1, cp, pk2(v.z, v.w));  fma2(acc1, sp, pk2(v.w, -v.z));
        }
        float2 a0 = unpk2(acc0), a1 = unpk2(acc1);
        ((float4*)sAcc)[kx*16 + c] = make_float4(a0.x, a0.y, a1.x, a1.y);
    }
    __syncthreads();
    {   // stage 2: per-mode complex channel mix, 2 kz per thread
        int kx = tid >> 4, o = tid & 15;
        float2 dv[2];
#pragma unroll
        for (int kzi = 0; kzi < 2; kzi++) {
            const float2* Wp = g_W + ((size_t)((kx*24 + ky)*12 + k0 + kzi)) * 256;
            float2 acc = make_float2(0.f, 0.f);
#pragma unroll
            for (int i = 0; i < 16; i++) {
                float2 av = sAcc[(kx*16 + i)*2 + kzi];
                float2 w  = Wp[i*16 + o];
                acc.x += av.x*w.x - av.y*w.y;
                acc.y += av.x*w.y + av.y*w.x;
            }
            dv[kzi] = acc;
        }
        float4* dst = (float4*)(g_D + (((size_t)(b*16 + o)*24 + ky)*24 + kx)*12 + k0);
        *dst = make_float4(dv[0].x, dv[0].y, dv[1].x, dv[1].y);
    }
}

// ---------------- kC: inverse X DFT (24 -> 64), parity, 2kz tile, packed (R5) ----------------
__global__ void __launch_bounds__(384) kC() {
    __shared__ float2 sD[2*292];
    __shared__ u64 sT1[792], sT2[792];
    int unit0 = blockIdx.x * 2;          // unit = bo*24 + ky
    int tid = threadIdx.x;
    for (int i = tid; i < 576; i += 384) {
        int un = i / 288, r = i % 288;
        sD[un*292 + r] = g_D[(size_t)(unit0 + un)*288 + r];
    }
    for (int i = tid; i < 792; i += 384) { sT1[i] = g_twI1[i]; sT2[i] = g_twI2[i]; }
    __syncthreads();

    int un = tid / 192, v = tid % 192;
    int x1 = v & 31, q = v >> 5, k0 = q * 2;
    const float2* D = sD + un*292;
    u64 Se[2], So[2];
    Se[0] = Se[1] = So[0] = So[1] = 0ull;

#pragma unroll 4
    for (int kx = 0; kx < 24; kx++) {
        float2 d0 = D[kx*12 + k0];
        float2 d1 = D[kx*12 + k0 + 1];
        u64 t1 = sT1[kx*33 + x1], t2 = sT2[kx*33 + x1];
        u64* tgt = (kx & 1) ? So : Se;
        fma2(tgt[0], t1, pk2(d0.x, d0.x)); fma2(tgt[0], t2, pk2(d0.y, d0.y));
        fma2(tgt[1], t1, pk2(d1.x, d1.x)); fma2(tgt[1], t2, pk2(d1.y, d1.y));
    }
    float2 se0 = unpk2(Se[0]), so0 = unpk2(So[0]);
    float2 se1 = unpk2(Se[1]), so1 = unpk2(So[1]);
    float4* base = (float4*)(g_Bf + (size_t)(unit0 + un)*768);  // [(bo*24+ky)*64+x][kz]
    base[(x1*12 + k0) >> 1]        = make_float4(se0.x + so0.x, se0.y + so0.y,
                                                se1.x + so1.x, se1.y + so1.y);
    base[((x1 + 32)*12 + k0) >> 1] = make_float4(se0.x - so0.x, se0.y - so0.y,
                                                se1.x - so1.x, se1.y - so1.y);
}

// ---------------- kD2: fused inv-Y + inv-T + ReLU + 16x16 mix + bias ----------------
// block = (b, xx); 512 threads; y in 4 chunks of 16 lines; 107 KB dyn smem -> 2 blocks/SM
#define KD2_SMEM ((4608 + 4608 + 3072 + 792 + 384 + 256)*8 + 64)
__global__ void __launch_bounds__(512, 2) kD2(const float* __restrict__ lo_w,
                                              const float* __restrict__ lo_b,
                                              float* __restrict__ out) {
    extern __shared__ u64 sm[];
    u64* sE1 = sm;                 // [c*288 + ky*12 + kz] = (re,re)
    u64* sE2 = sE1 + 4608;         //                      = (im,im)
    u64* sF  = sE2 + 4608;         // [(c*16 + line)*12 + k] packed (re,im)
    u64* sT1 = sF + 3072;          // (c,s) inv twiddles, pad 33
    u64* sTi = sT1 + 792;          // inv-T (A,B)
    u64* sWq = sTi + 384;          // lo_w dup-packed
    float* sB = (float*)(sWq + 256);

    int tid = threadIdx.x;
    int b = blockIdx.x >> 6, xx = blockIdx.x & 63;

    for (int i = tid; i < 4608; i += 512) {
        int c = i / 288, r = i % 288;              // r = ky*12 + kz
        int ky = r / 12, kz = r % 12;
        float2 d = g_Bf[((size_t)((b*16 + c)*24 + ky)*64 + xx)*12 + kz];
        sE1[i] = pk2(d.x, d.x);
        sE2[i] = pk2(d.y, d.y);
    }
    for (int i = tid; i < 792; i += 512) sT1[i] = g_twI1[i];
    for (int i = tid; i < 384; i += 512) sTi[i] = ((const u64*)g_twTi2)[i];
    if (tid < 256) { float w = lo_w[tid]; sWq[tid] = pk2(w, w); }
    if (tid < 16)  sB[tid] = lo_b[tid];
    __syncthreads();

    int c  = tid >> 5;                 // phase-1 channel (warp-uniform)
    int l  = (tid >> 2) & 7;           // phase-1 y1 local
    int q  = tid & 3;                  // phase-1 kz triple
    int k0 = q * 3;
    int w    = tid >> 5;               // phase-2 warp = line
    int lane = tid & 31;

    for (int a = 0; a < 4; a++) {
        // ---- phase 1: inverse Y (parity), write 16 lines into sF ----
        {
            int y1 = 8*a + l;
            const u64* E1 = sE1 + c*288;
            const u64* E2 = sE2 + c*288;
            u64 Se[3], So[3];
            Se[0]=Se[1]=Se[2]=0ull; So[0]=So[1]=So[2]=0ull;
#pragma unroll 4
            for (int ky = 0; ky < 24; ky++) {
                u64 t1 = sT1[ky*33 + y1];
                float2 f = unpk2(t1);
                u64 t2 = pk2(-f.y, f.x);
                u64* tgt = (ky & 1) ? So : Se;
                const u64* e1 = E1 + ky*12 + k0;
                const u64* e2 = E2 + ky*12 + k0;
#pragma unroll
                for (int z = 0; z < 3; z++) { fma2(tgt[z], t1, e1[z]); fma2(tgt[z], t2, e2[z]); }
            }
#pragma unroll
            for (int z = 0; z < 3; z++) {
                float2 se = unpk2(Se[z]), so = unpk2(So[z]);
                sF[(c*16 + l)*12 + k0 + z]     = pk2(se.x + so.x, se.y + so.y);
                sF[(c*16 + l + 8)*12 + k0 + z] = pk2(se.x - so.x, se.y - so.y);
            }
        }
        __syncthreads();

        // ---- phase 2: inverse T (parity) + ReLU + packed 1x1 mix; warp = line ----
        {
            int y = 8*a + (w & 7) + ((w & 8) ? 32 : 0);
            u64 p[16];
#pragma unroll
            for (int qt = 0; qt < 4; qt++) {
                u64 aE[4], aO[4];
                aE[0]=aE[1]=aE[2]=aE[3]=0ull;
                aO[0]=aO[1]=aO[2]=aO[3]=0ull;
#pragma unroll
                for (int k = 0; k < 12; k++) {
                    u64 ti = sTi[k*32 + lane];
#pragma unroll
                    for (int c4 = 0; c4 < 4; c4++) {
                        u64 f = sF[((qt*4 + c4)*16 + w)*12 + k];   // warp-uniform broadcast
                        if (k & 1) fma2(aO[c4], f, ti);
                        else       fma2(aE[c4], f, ti);
                    }
                }
#pragma unroll
                for (int c4 = 0; c4 < 4; c4++) {
                    float2 e = unpk2(aE[c4]), o = unpk2(aO[c4]);
                    float Ev = e.x + e.y, Ov = o.x + o.y;
                    p[qt*4 + c4] = pk2(fmaxf(Ev + Ov, 0.f), fmaxf(Ev - Ov, 0.f));
                }
            }
#pragma unroll
            for (int o = 0; o < 16; o++) {
                u64 acc = pk2(sB[o], sB[o]);
#pragma unroll
                for (int cc = 0; cc < 16; cc++) fma2(acc, sWq[o*16 + cc], p[cc]);
                float2 rv = unpk2(acc);
                float* dst = out + (((size_t)(b*16 + o)*64 + xx)*64 + y)*64;
                dst[lane]      = rv.x;
                dst[lane + 32] = rv.y;
            }
        }
        __syncthreads();
    }
}

// ---------------- launch ----------------
extern "C" void kernel_launch(void* const* d_in, const int* in_sizes, int n_in,
                              void* d_out, int out_size) {
    const float* x    = (const float*)d_in[0];
    const float* w1   = (const float*)d_in[1];
    const float* w2   = (const float*)d_in[2];
    const float* w3   = (const float*)d_in[3];
    const float* w4   = (const float*)d_in[4];
    const float* lo_w = (const float*)d_in[5];
    const float* lo_b = (const float*)d_in[6];
    float* out = (float*)d_out;

    cudaFuncSetAttribute(kA2, cudaFuncAttributeMaxDynamicSharedMemorySize, KA2_SMEM);
    cudaFuncSetAttribute(kD2, cudaFuncAttributeMaxDynamicSharedMemorySize, KD2_SMEM);

    k_init<<<5, 256>>>();
    k_repack2<<<144, 256>>>(w1, w2, w3, w4);
    kA2<<<4096, 256, KA2_SMEM>>>(x);                 // T 64->12 + Y 64->24 fused
    kB<<<1152, 384>>>();                             // X 64->24 + channel mix (2kz tile)
    kC<<<1536, 384>>>();                             // X 24->64
    kD2<<<512, 512, KD2_SMEM>>>(lo_w, lo_b, out);    // Y 24->64 + T 12->64 + relu + 1x1 fused
}

// round 8
// speedup vs baseline: 1.5025x; 1.0174x over previous
#include <cuda_runtime.h>
#include <math.h>

#define N3INV (1.0f/262144.0f)
typedef unsigned long long u64;

// ---------------- scratch (static device memory; no allocations) ----------------
__device__ float2 g_Bm[8*24*12*1024];    // 19 MB: fwd Y out, mode-major [((b*24+ky)*12+kz)*1024 + c*64+x]
__device__ float2 g_Bf[8*16*64*24*12];   // 19 MB: inv-X out [(bo*24+ky)*64+x][kz]
__device__ float2 g_W [24*24*12*16*16];  // 14 MB: repacked weights, mode-major
__device__ u64    g_twTpk[12*32];        // fwd T: (c, -s) packed
__device__ float2 g_twTi2[12*32];        // inv T: (A, B) = (2c/N^3, -2s/N^3); k=0: (1/N^3, 0)
__device__ float2 g_twXY [24*33];        // X/Y: (c, s)  [padded stride 33] (fwd + inv shared)

// ---------------- f32x2 packed helpers ----------------
__device__ __forceinline__ u64 pk2(float lo, float hi){
    u64 r; asm("mov.b64 %0, {%1,%2};" : "=l"(r) : "f"(lo), "f"(hi)); return r;
}
__device__ __forceinline__ void fma2(u64& d, u64 a, u64 b){
    asm("fma.rn.f32x2 %0, %1, %2, %0;" : "+l"(d) : "l"(a), "l"(b));
}
__device__ __forceinline__ float2 unpk2(u64 v){
    float2 f; asm("mov.b64 {%0,%1}, %2;" : "=f"(f.x), "=f"(f.y) : "l"(v)); return f;
}

// ---------------- init + repack merged: blocks 0-143 repack, block 144 twiddles ----------------
__global__ void __launch_bounds__(256) k_initrepack(const float* __restrict__ w1, const float* __restrict__ w2,
                                                    const float* __restrict__ w3, const float* __restrict__ w4) {
    int tid = threadIdx.x;
    if (blockIdx.x == 144) {
        for (int idx = tid; idx < 384 + 792; idx += 256) {
            if (idx < 384) {
                int k = idx >> 5, t = idx & 31;
                float s, c;
                sincospif((float)((k * t) & 63) / 32.0f, &s, &c);
                g_twTpk[idx] = pk2(c, -s);
                g_twTi2[idx] = (k == 0) ? make_float2(N3INV, 0.0f)
                                        : make_float2(2.0f*c*N3INV, -2.0f*s*N3INV);
            } else {
                int r = idx - 384;
                int j = r / 33, u = r % 33;
                int uu = (u < 32) ? u : 0;
                int f = (j < 12) ? j : j + 40;   // freqs 0..11, 52..63
                float s, c;
                sincospif((float)((f * uu) & 63) / 32.0f, &s, &c);
                g_twXY[r] = make_float2(c, s);
            }
        }
        return;
    }
    int jx = blockIdx.x / 12, jy = blockIdx.x % 12;
#pragma unroll
    for (int q = 0; q < 4; q++) {
        const float* w = (q == 0) ? w1 : (q == 1) ? w2 : (q == 2) ? w3 : w4;
        const float4* src = (const float4*)(w + ((size_t)tid*1728 + (jx*12 + jy)*12)*2);
        float2 r[12];
#pragma unroll
        for (int j = 0; j < 6; j++) {
            float4 v = src[j];
            r[2*j]   = make_float2(v.x, v.y);
            r[2*j+1] = make_float2(v.z, v.w);
        }
        int kxi = jx + ((q & 1) ? 12 : 0);
        int kyi = jy + ((q & 2) ? 12 : 0);
        float2* dst = g_W + ((size_t)(kxi*24 + kyi)*12)*256 + tid;
#pragma unroll
        for (int j = 0; j < 12; j++) dst[j*256] = r[j];
    }
}

// ---------------- kA2: fused T-DFT (radix-2) + Y-DFT (radix-2) ----------------
// block = 2 slabs of (b,c,x); 256 threads; dynamic smem 54 KB -> 4 blocks/SM
#define KA2_SMEM (2*4160*4 + 2*792*8 + 384*8 + 792*8)
__global__ void __launch_bounds__(256, 4) kA2(const float* __restrict__ x) {
    extern __shared__ char smraw[];
    float*  sx  = (float*)smraw;
    float2* sA  = (float2*)(smraw + 2*4160*4);
    u64*    stT = (u64*)(smraw + 2*4160*4 + 2*792*8);
    float2* stY = (float2*)(smraw + 2*4160*4 + 2*792*8 + 384*8);
    float2* sEO = (float2*)sx;           // reused after T-phase: [sl*804 + p*396 + k*33 + y1]

    int slab0 = blockIdx.x * 2;
    int tid = threadIdx.x;

    const float4* xs = (const float4*)(x + (size_t)slab0 * 4096);
    for (int i = tid; i < 2048; i += 256) {
        float4 v = xs[i];
        int sl = i >> 10, r = i & 1023;
        int yy = r >> 4, t4 = (r & 15) * 4;
        float* row = &sx[sl*4160 + yy*65 + t4];
        row[0] = v.x; row[1] = v.y; row[2] = v.z; row[3] = v.w;
    }
    for (int i = tid; i < 384; i += 256) stT[i] = g_twTpk[i];
    for (int i = tid; i < 792; i += 256) stY[i] = g_twXY[i];
    __syncthreads();

    // ---- phase T: radix-2 in-loop, thread = (sl, yy, khalf), 6 kz each ----
    {
        int sl = tid >> 7, g = (tid >> 6) & 1, yy = tid & 63;
        int kb = g * 6;
        const float* row = &sx[sl*4160 + yy*65];
        u64 acc[6];
#pragma unroll
        for (int j = 0; j < 6; j++) acc[j] = 0ull;
#pragma unroll 4
        for (int t1 = 0; t1 < 32; t1++) {
            float a = row[t1], b = row[t1 + 32];
            float E = a + b, O = a - b;
            u64 pE = pk2(E, E), pO = pk2(O, O);
#pragma unroll
            for (int j = 0; j < 6; j++) {
                int k = kb + j;
                fma2(acc[j], stT[k*32 + t1], (k & 1) ? pO : pE);
            }
        }
        float2* dst = sA + sl*792 + yy;
#pragma unroll
        for (int j = 0; j < 6; j++) dst[(kb + j)*66] = unpk2(acc[j]);
    }
    __syncthreads();

    // ---- phase EO over y: sA raw -> sEO (in sx region) ----
    for (int i = tid; i < 768; i += 256) {
        int sl = (i >= 384);
        int r  = i - sl*384;                      // r = k*32 + y1
        int k = r >> 5, y1 = r & 31;
        float2 a = sA[sl*792 + k*66 + y1];
        float2 b = sA[sl*792 + k*66 + 32 + y1];
        sEO[sl*804 + k*33 + y1]       = make_float2(a.x + b.x, a.y + b.y);
        sEO[sl*804 + 396 + k*33 + y1] = make_float2(a.x - b.x, a.y - b.y);
    }
    __syncthreads();

    // ---- phase Y: 144 threads: (ky, kz-pair), both slabs -> float4 writes ----
    if (tid < 144) {
        int ky = tid / 6, q = tid % 6, k0 = q * 2;
        int p = ky & 1;
        const float2* tw = stY + ky*33;
        const float2* dat0 = sEO + p*396 + k0*33;
        const float2* dat1 = sEO + 804 + p*396 + k0*33;
        u64 acc0[2], acc1[2];
        acc0[0] = acc0[1] = acc1[0] = acc1[1] = 0ull;
#pragma unroll 4
        for (int y1 = 0; y1 < 32; y1++) {
            float2 w = tw[y1];
            u64 cp = pk2(w.x, w.x), sp = pk2(w.y, w.y);
#pragma unroll
            for (int z = 0; z < 2; z++) {
                float2 v0 = dat0[z*33 + y1];
                fma2(acc0[z], cp, pk2(v0.x, v0.y));
                fma2(acc0[z], sp, pk2(v0.y, -v0.x));
                float2 v1 = dat1[z*33 + y1];
                fma2(acc1[z], cp, pk2(v1.x, v1.y));
                fma2(acc1[z], sp, pk2(v1.y, -v1.x));
            }
        }
        int bb = slab0 >> 10, cc = (slab0 >> 6) & 15, xx0 = slab0 & 63;
#pragma unroll
        for (int z = 0; z < 2; z++) {
            float2 r0 = unpk2(acc0[z]), r1 = unpk2(acc1[z]);
            float4* dst = (float4*)(g_Bm + ((size_t)(bb*24 + ky)*12 + k0 + z)*1024 + cc*64 + xx0);
            *dst = make_float4(r0.x, r0.y, r1.x, r1.y);
        }
    }
}

// ---------------- kBC: X-DFT (radix-2) + spectral 16x16 mix + inverse X-DFT, fused ----------------
// block = (b, ky, kz-pair); grid 1152; 512 threads; ~35 KB smem -> 4 blocks/SM
__global__ void __launch_bounds__(512) kBC() {
    __shared__ float2 sIn[16*65*2];      // [(c*65+xx)*2 + kzi]  (float4 view: [c*65+xx])
    __shared__ float2 sAcc[24*16*2];     // fwd modes  [(kx*16+c)*2 + kzi]
    __shared__ float2 sMix[24*16*2];     // mixed modes [(kx*16+o)*2 + kzi]
    __shared__ float2 stX[792];          // (c,s), serves forward and inverse
    int blk = blockIdx.x;
    int b = blk / 144, r = blk % 144;
    int ky = r / 6, q = r % 6;
    int k0 = q * 2;
    int tid = threadIdx.x;

    const float4* src = (const float4*)(g_Bm + ((size_t)(b*24 + ky)*12 + k0)*1024);
    for (int i = tid; i < 1024; i += 512) {
        int kzi = i >> 9, j = i & 511;
        float4 v = src[kzi*512 + j];
        int c = j >> 5, x2 = (j & 31)*2;
        int base = (c*65 + x2)*2 + kzi;
        sIn[base]     = make_float2(v.x, v.y);
        sIn[base + 2] = make_float2(v.z, v.w);
    }
    for (int i = tid; i < 792; i += 512) stX[i] = g_twXY[i];
    __syncthreads();

    // EO over x (both kz at once via float4); exactly 512 threads
    float4* sIn4 = (float4*)sIn;
    {
        int c = tid >> 5, x1 = tid & 31;
        float4 a = sIn4[c*65 + x1], bb4 = sIn4[c*65 + x1 + 32];
        sIn4[c*65 + x1]      = make_float4(a.x + bb4.x, a.y + bb4.y, a.z + bb4.z, a.w + bb4.w);
        sIn4[c*65 + x1 + 32] = make_float4(a.x - bb4.x, a.y - bb4.y, a.z - bb4.z, a.w - bb4.w);
    }
    __syncthreads();

    if (tid < 384) {   // stage 1: X DFT -> sAcc[kx][c][2kz]
        int kx = tid >> 4, c = tid & 15;
        const float4* rowp = sIn4 + c*65 + (kx & 1)*32;
        const float2* tw = &stX[kx*33];
        u64 acc0 = 0ull, acc1 = 0ull;    // packed (re,im) per kz
#pragma unroll 4
        for (int x1 = 0; x1 < 32; x1++) {
            float4 v = rowp[x1];
            float2 w = tw[x1];
            u64 cp = pk2(w.x, w.x), sp = pk2(w.y, w.y);
            fma2(acc0, cp, pk2(v.x, v.y));  fma2(acc0, sp, pk2(v.y, -v.x));
            fma2(acc1, cp, pk2(v.z, v.w));  fma2(acc1, sp, pk2(v.w, -v.z));
        }
        float2 a0 = unpk2(acc0), a1 = unpk2(acc1);
        ((float4*)sAcc)[kx*16 + c] = make_float4(a0.x, a0.y, a1.x, a1.y);
    }
    __syncthreads();
    if (tid < 384) {   // stage 2: per-mode complex channel mix -> sMix
        int kx = tid >> 4, o = tid & 15;
        float2 dv[2];
#pragma unroll
        for (int kzi = 0; kzi < 2; kzi++) {
            const float2* Wp = g_W + ((size_t)((kx*24 + ky)*12 + k0 + kzi)) * 256;
            float2 acc = make_float2(0.f, 0.f);
#pragma unroll
            for (int i = 0; i < 16; i++) {
                float2 av = sAcc[(kx*16 + i)*2 + kzi];
                float2 w  = Wp[i*16 + o];
                acc.x += av.x*w.x - av.y*w.y;
                acc.y += av.x*w.y + av.y*w.x;
            }
            dv[kzi] = acc;
        }
        ((float4*)sMix)[kx*16 + o] = make_float4(dv[0].x, dv[0].y, dv[1].x, dv[1].y);
    }
    __syncthreads();

    {   // stage 3: inverse X DFT (parity); thread = (o, x1); full 512
        int o = tid >> 5, x1 = tid & 31;
        const u64* stX64 = (const u64*)stX;
        u64 Se[2], So[2];
        Se[0] = Se[1] = So[0] = So[1] = 0ull;
#pragma unroll 4
        for (int kx = 0; kx < 24; kx++) {
            u64 t1 = stX64[kx*33 + x1];
            float2 f = unpk2(t1);
            u64 t2 = pk2(-f.y, f.x);
            u64* tgt = (kx & 1) ? So : Se;
            const float2* dm = sMix + (kx*16 + o)*2;
#pragma unroll
            for (int kzi = 0; kzi < 2; kzi++) {
                float2 d = dm[kzi];                 // broadcast within warp
                fma2(tgt[kzi], t1, pk2(d.x, d.x));
                fma2(tgt[kzi], t2, pk2(d.y, d.y));
            }
        }
        float2 se0 = unpk2(Se[0]), so0 = unpk2(So[0]);
        float2 se1 = unpk2(Se[1]), so1 = unpk2(So[1]);
        float4* base = (float4*)(g_Bf + (size_t)((b*16 + o)*24 + ky)*768);  // [(bo*24+ky)*64+x][kz]
        base[(x1*12 + k0) >> 1]        = make_float4(se0.x + so0.x, se0.y + so0.y,
                                                    se1.x + so1.x, se1.y + so1.y);
        base[((x1 + 32)*12 + k0) >> 1] = make_float4(se0.x - so0.x, se0.y - so0.y,
                                                    se1.x - so1.x, se1.y - so1.y);
    }
}

// ---------------- kD2: fused inv-Y + inv-T + ReLU + 16x16 mix + bias ----------------
// block = (b, xx); 512 threads; y in 4 chunks of 16 lines; 107 KB dyn smem -> 2 blocks/SM
#define KD2_SMEM ((4608 + 4608 + 3072 + 792 + 384 + 256)*8 + 64)
__global__ void __launch_bounds__(512, 2) kD2(const float* __restrict__ lo_w,
                                              const float* __restrict__ lo_b,
                                              float* __restrict__ out) {
    extern __shared__ u64 sm[];
    u64* sE1 = sm;                 // [c*288 + ky*12 + kz] = (re,re)
    u64* sE2 = sE1 + 4608;         //                      = (im,im)
    u64* sF  = sE2 + 4608;         // [(c*16 + line)*12 + k] packed (re,im)
    u64* sT1 = sF + 3072;          // (c,s) inv twiddles, pad 33
    u64* sTi = sT1 + 792;          // inv-T (A,B)
    u64* sWq = sTi + 384;          // lo_w dup-packed
    float* sB = (float*)(sWq + 256);

    int tid = threadIdx.x;
    int b = blockIdx.x >> 6, xx = blockIdx.x & 63;

    for (int i = tid; i < 4608; i += 512) {
        int c = i / 288, r = i % 288;              // r = ky*12 + kz
        int ky = r / 12, kz = r % 12;
        float2 d = g_Bf[((size_t)((b*16 + c)*24 + ky)*64 + xx)*12 + kz];
        sE1[i] = pk2(d.x, d.x);
        sE2[i] = pk2(d.y, d.y);
    }
    for (int i = tid; i < 792; i += 512) sT1[i] = ((const u64*)g_twXY)[i];
    for (int i = tid; i < 384; i += 512) sTi[i] = ((const u64*)g_twTi2)[i];
    if (tid < 256) { float w = lo_w[tid]; sWq[tid] = pk2(w, w); }
    if (tid < 16)  sB[tid] = lo_b[tid];
    __syncthreads();

    int c  = tid >> 5;                 // phase-1 channel (warp-uniform)
    int l  = (tid >> 2) & 7;           // phase-1 y1 local
    int q  = tid & 3;                  // phase-1 kz triple
    int k0 = q * 3;
    int w    = tid >> 5;               // phase-2 warp = line
    int lane = tid & 31;

    for (int a = 0; a < 4; a++) {
        // ---- phase 1: inverse Y (parity), write 16 lines into sF ----
        {
            int y1 = 8*a + l;
            const u64* E1 = sE1 + c*288;
            const u64* E2 = sE2 + c*288;
            u64 Se[3], So[3];
            Se[0]=Se[1]=Se[2]=0ull; So[0]=So[1]=So[2]=0ull;
#pragma unroll 4
            for (int ky = 0; ky < 24; ky++) {
                u64 t1 = sT1[ky*33 + y1];
                float2 f = unpk2(t1);
                u64 t2 = pk2(-f.y, f.x);
                u64* tgt = (ky & 1) ? So : Se;
                const u64* e1 = E1 + ky*12 + k0;
                const u64* e2 = E2 + ky*12 + k0;
#pragma unroll
                for (int z = 0; z < 3; z++) { fma2(tgt[z], t1, e1[z]); fma2(tgt[z], t2, e2[z]); }
            }
#pragma unroll
            for (int z = 0; z < 3; z++) {
                float2 se = unpk2(Se[z]), so = unpk2(So[z]);
                sF[(c*16 + l)*12 + k0 + z]     = pk2(se.x + so.x, se.y + so.y);
                sF[(c*16 + l + 8)*12 + k0 + z] = pk2(se.x - so.x, se.y - so.y);
            }
        }
        __syncthreads();

        // ---- phase 2: inverse T (parity) + ReLU + packed 1x1 mix; warp = line ----
        {
            int y = 8*a + (w & 7) + ((w & 8) ? 32 : 0);
            u64 p[16];
#pragma unroll
            for (int qt = 0; qt < 4; qt++) {
                u64 aE[4], aO[4];
                aE[0]=aE[1]=aE[2]=aE[3]=0ull;
                aO[0]=aO[1]=aO[2]=aO[3]=0ull;
#pragma unroll
                for (int k = 0; k < 12; k++) {
                    u64 ti = sTi[k*32 + lane];
#pragma unroll
                    for (int c4 = 0; c4 < 4; c4++) {
                        u64 f = sF[((qt*4 + c4)*16 + w)*12 + k];   // warp-uniform broadcast
                        if (k & 1) fma2(aO[c4], f, ti);
                        else       fma2(aE[c4], f, ti);
                    }
                }
#pragma unroll
                for (int c4 = 0; c4 < 4; c4++) {
                    float2 e = unpk2(aE[c4]), o = unpk2(aO[c4]);
                    float Ev = e.x + e.y, Ov = o.x + o.y;
                    p[qt*4 + c4] = pk2(fmaxf(Ev + Ov, 0.f), fmaxf(Ev - Ov, 0.f));
                }
            }
#pragma unroll
            for (int o = 0; o < 16; o++) {
                u64 acc = pk2(sB[o], sB[o]);
#pragma unroll
                for (int cc = 0; cc < 16; cc++) fma2(acc, sWq[o*16 + cc], p[cc]);
                float2 rv = unpk2(acc);
                float* dst = out + (((size_t)(b*16 + o)*64 + xx)*64 + y)*64;
                dst[lane]      = rv.x;
                dst[lane + 32] = rv.y;
            }
        }
        __syncthreads();
    }
}

// ---------------- launch ----------------
extern "C" void kernel_launch(void* const* d_in, const int* in_sizes, int n_in,
                              void* d_out, int out_size) {
    const float* x    = (const float*)d_in[0];
    const float* w1   = (const float*)d_in[1];
    const float* w2   = (const float*)d_in[2];
    const float* w3   = (const float*)d_in[3];
    const float* w4   = (const float*)d_in[4];
    const float* lo_w = (const float*)d_in[5];
    const float* lo_b = (const float*)d_in[6];
    float* out = (float*)d_out;

    cudaFuncSetAttribute(kA2, cudaFuncAttributeMaxDynamicSharedMemorySize, KA2_SMEM);
    cudaFuncSetAttribute(kD2, cudaFuncAttributeMaxDynamicSharedMemorySize, KD2_SMEM);

    k_initrepack<<<145, 256>>>(w1, w2, w3, w4);
    kA2<<<4096, 256, KA2_SMEM>>>(x);                 // T 64->12 + Y 64->24 fused
    kBC<<<1152, 512>>>();                            // X 64->24 + channel mix + X 24->64 fused
    kD2<<<512, 512, KD2_SMEM>>>(lo_w, lo_b, out);    // Y 24->64 + T 12->64 + relu + 1x1 fused
}

// round 9
// speedup vs baseline: 1.6065x; 1.0692x over previous
#include <cuda_runtime.h>
#include <math.h>

#define N3INV (1.0f/262144.0f)
typedef unsigned long long u64;

// ---------------- scratch (static device memory; no allocations) ----------------
__device__ float2 g_Bm[8*24*12*1024];    // 19 MB: fwd Y out, mode-major [((b*24+ky)*12+kz)*1024 + c*64+x]
__device__ float2 g_Bf[8*16*64*24*12];   // 19 MB: inv-X out [(bo*24+ky)*64+x][kz]
__device__ float2 g_W [24*24*12*16*16];  // 14 MB: repacked weights, mode-major
__device__ u64    g_twTpk[12*32];        // fwd T: (c, -s) packed
__device__ float2 g_twTi2[12*32];        // inv T: (A, B) = (2c/N^3, -2s/N^3); k=0: (1/N^3, 0)
__device__ float2 g_twXY [24*33];        // X/Y: (c, s)  [padded stride 33] (fwd + inv shared)

// ---------------- f32x2 packed helpers ----------------
__device__ __forceinline__ u64 pk2(float lo, float hi){
    u64 r; asm("mov.b64 %0, {%1,%2};" : "=l"(r) : "f"(lo), "f"(hi)); return r;
}
__device__ __forceinline__ void fma2(u64& d, u64 a, u64 b){
    asm("fma.rn.f32x2 %0, %1, %2, %0;" : "+l"(d) : "l"(a), "l"(b));
}
__device__ __forceinline__ float2 unpk2(u64 v){
    float2 f; asm("mov.b64 {%0,%1}, %2;" : "=f"(f.x), "=f"(f.y) : "l"(v)); return f;
}

// ---------------- init + repack merged: blocks 0-143 repack, block 144 twiddles ----------------
__global__ void __launch_bounds__(256) k_initrepack(const float* __restrict__ w1, const float* __restrict__ w2,
                                                    const float* __restrict__ w3, const float* __restrict__ w4) {
    int tid = threadIdx.x;
    if (blockIdx.x == 144) {
        for (int idx = tid; idx < 384 + 792; idx += 256) {
            if (idx < 384) {
                int k = idx >> 5, t = idx & 31;
                float s, c;
                sincospif((float)((k * t) & 63) / 32.0f, &s, &c);
                g_twTpk[idx] = pk2(c, -s);
                g_twTi2[idx] = (k == 0) ? make_float2(N3INV, 0.0f)
                                        : make_float2(2.0f*c*N3INV, -2.0f*s*N3INV);
            } else {
                int r = idx - 384;
                int j = r / 33, u = r % 33;
                int uu = (u < 32) ? u : 0;
                int f = (j < 12) ? j : j + 40;   // freqs 0..11, 52..63
                float s, c;
                sincospif((float)((f * uu) & 63) / 32.0f, &s, &c);
                g_twXY[r] = make_float2(c, s);
            }
        }
        return;
    }
    int jx = blockIdx.x / 12, jy = blockIdx.x % 12;
#pragma unroll
    for (int q = 0; q < 4; q++) {
        const float* w = (q == 0) ? w1 : (q == 1) ? w2 : (q == 2) ? w3 : w4;
        const float4* src = (const float4*)(w + ((size_t)tid*1728 + (jx*12 + jy)*12)*2);
        float2 r[12];
#pragma unroll
        for (int j = 0; j < 6; j++) {
            float4 v = src[j];
            r[2*j]   = make_float2(v.x, v.y);
            r[2*j+1] = make_float2(v.z, v.w);
        }
        int kxi = jx + ((q & 1) ? 12 : 0);
        int kyi = jy + ((q & 2) ? 12 : 0);
        float2* dst = g_W + ((size_t)(kxi*24 + kyi)*12)*256 + tid;
#pragma unroll
        for (int j = 0; j < 12; j++) dst[j*256] = r[j];
    }
}

// ---------------- kA2: fused T-DFT (radix-2) + Y-DFT (radix-2) ----------------
// block = 2 slabs of (b,c,x); 256 threads; dynamic smem 54 KB -> 4 blocks/SM
#define KA2_SMEM (2*4160*4 + 2*792*8 + 384*8 + 792*8)
__global__ void __launch_bounds__(256, 4) kA2(const float* __restrict__ x) {
    extern __shared__ char smraw[];
    float*  sx  = (float*)smraw;
    float2* sA  = (float2*)(smraw + 2*4160*4);
    u64*    stT = (u64*)(smraw + 2*4160*4 + 2*792*8);
    float2* stY = (float2*)(smraw + 2*4160*4 + 2*792*8 + 384*8);
    float2* sEO = (float2*)sx;           // reused after T-phase: [sl*804 + p*396 + k*33 + y1]

    int slab0 = blockIdx.x * 2;
    int tid = threadIdx.x;

    const float4* xs = (const float4*)(x + (size_t)slab0 * 4096);
    for (int i = tid; i < 2048; i += 256) {
        float4 v = xs[i];
        int sl = i >> 10, r = i & 1023;
        int yy = r >> 4, t4 = (r & 15) * 4;
        float* row = &sx[sl*4160 + yy*65 + t4];
        row[0] = v.x; row[1] = v.y; row[2] = v.z; row[3] = v.w;
    }
    for (int i = tid; i < 384; i += 256) stT[i] = g_twTpk[i];
    for (int i = tid; i < 792; i += 256) stY[i] = g_twXY[i];
    __syncthreads();

    // ---- phase T: radix-2 in-loop, thread = (sl, yy, khalf), 6 kz each ----
    {
        int sl = tid >> 7, g = (tid >> 6) & 1, yy = tid & 63;
        int kb = g * 6;
        const float* row = &sx[sl*4160 + yy*65];
        u64 acc[6];
#pragma unroll
        for (int j = 0; j < 6; j++) acc[j] = 0ull;
#pragma unroll 4
        for (int t1 = 0; t1 < 32; t1++) {
            float a = row[t1], b = row[t1 + 32];
            float E = a + b, O = a - b;
            u64 pE = pk2(E, E), pO = pk2(O, O);
#pragma unroll
            for (int j = 0; j < 6; j++) {
                int k = kb + j;
                fma2(acc[j], stT[k*32 + t1], (k & 1) ? pO : pE);
            }
        }
        float2* dst = sA + sl*792 + yy;
#pragma unroll
        for (int j = 0; j < 6; j++) dst[(kb + j)*66] = unpk2(acc[j]);
    }
    __syncthreads();

    // ---- phase EO over y: sA raw -> sEO (in sx region) ----
    for (int i = tid; i < 768; i += 256) {
        int sl = (i >= 384);
        int r  = i - sl*384;                      // r = k*32 + y1
        int k = r >> 5, y1 = r & 31;
        float2 a = sA[sl*792 + k*66 + y1];
        float2 b = sA[sl*792 + k*66 + 32 + y1];
        sEO[sl*804 + k*33 + y1]       = make_float2(a.x + b.x, a.y + b.y);
        sEO[sl*804 + 396 + k*33 + y1] = make_float2(a.x - b.x, a.y - b.y);
    }
    __syncthreads();

    // ---- phase Y: 144 threads: (ky, kz-pair), both slabs -> float4 writes ----
    if (tid < 144) {
        int ky = tid / 6, q = tid % 6, k0 = q * 2;
        int p = ky & 1;
        const float2* tw = stY + ky*33;
        const float2* dat0 = sEO + p*396 + k0*33;
        const float2* dat1 = sEO + 804 + p*396 + k0*33;
        u64 acc0[2], acc1[2];
        acc0[0] = acc0[1] = acc1[0] = acc1[1] = 0ull;
#pragma unroll 4
        for (int y1 = 0; y1 < 32; y1++) {
            float2 w = tw[y1];
            u64 cp = pk2(w.x, w.x), sp = pk2(w.y, w.y);
#pragma unroll
            for (int z = 0; z < 2; z++) {
                float2 v0 = dat0[z*33 + y1];
                fma2(acc0[z], cp, pk2(v0.x, v0.y));
                fma2(acc0[z], sp, pk2(v0.y, -v0.x));
                float2 v1 = dat1[z*33 + y1];
                fma2(acc1[z], cp, pk2(v1.x, v1.y));
                fma2(acc1[z], sp, pk2(v1.y, -v1.x));
            }
        }
        int bb = slab0 >> 10, cc = (slab0 >> 6) & 15, xx0 = slab0 & 63;
#pragma unroll
        for (int z = 0; z < 2; z++) {
            float2 r0 = unpk2(acc0[z]), r1 = unpk2(acc1[z]);
            float4* dst = (float4*)(g_Bm + ((size_t)(bb*24 + ky)*12 + k0 + z)*1024 + cc*64 + xx0);
            *dst = make_float4(r0.x, r0.y, r1.x, r1.y);
        }
    }
}

// ---------------- kBC: X-DFT (radix-2) + spectral 16x16 mix + inverse X-DFT, fused ----------------
// block = (b, ky, kz-pair); grid 1152; 512 threads; ~35 KB smem -> 4 blocks/SM
__global__ void __launch_bounds__(512) kBC() {
    __shared__ float2 sIn[16*65*2];      // [(c*65+xx)*2 + kzi]  (float4 view: [c*65+xx])
    __shared__ float2 sAcc[24*16*2];     // fwd modes  [(kx*16+c)*2 + kzi]
    __shared__ float2 sMix[24*16*2];     // mixed modes [(kx*16+o)*2 + kzi]
    __shared__ float2 stX[792];          // (c,s), serves forward and inverse
    int blk = blockIdx.x;
    int b = blk / 144, r = blk % 144;
    int ky = r / 6, q = r % 6;
    int k0 = q * 2;
    int tid = threadIdx.x;

    const float4* src = (const float4*)(g_Bm + ((size_t)(b*24 + ky)*12 + k0)*1024);
    for (int i = tid; i < 1024; i += 512) {
        int kzi = i >> 9, j = i & 511;
        float4 v = src[kzi*512 + j];
        int c = j >> 5, x2 = (j & 31)*2;
        int base = (c*65 + x2)*2 + kzi;
        sIn[base]     = make_float2(v.x, v.y);
        sIn[base + 2] = make_float2(v.z, v.w);
    }
    for (int i = tid; i < 792; i += 512) stX[i] = g_twXY[i];
    __syncthreads();

    // EO over x (both kz at once via float4); exactly 512 threads
    float4* sIn4 = (float4*)sIn;
    {
        int c = tid >> 5, x1 = tid & 31;
        float4 a = sIn4[c*65 + x1], bb4 = sIn4[c*65 + x1 + 32];
        sIn4[c*65 + x1]      = make_float4(a.x + bb4.x, a.y + bb4.y, a.z + bb4.z, a.w + bb4.w);
        sIn4[c*65 + x1 + 32] = make_float4(a.x - bb4.x, a.y - bb4.y, a.z - bb4.z, a.w - bb4.w);
    }
    __syncthreads();

    if (tid < 384) {   // stage 1: X DFT -> sAcc[kx][c][2kz]
        int kx = tid >> 4, c = tid & 15;
        const float4* rowp = sIn4 + c*65 + (kx & 1)*32;
        const float2* tw = &stX[kx*33];
        u64 acc0 = 0ull, acc1 = 0ull;    // packed (re,im) per kz
#pragma unroll 4
        for (int x1 = 0; x1 < 32; x1++) {
            float4 v = rowp[x1];
            float2 w = tw[x1];
            u64 cp = pk2(w.x, w.x), sp = pk2(w.y, w.y);
            fma2(acc0, cp, pk2(v.x, v.y));  fma2(acc0, sp, pk2(v.y, -v.x));
            fma2(acc1, cp, pk2(v.z, v.w));  fma2(acc1, sp, pk2(v.w, -v.z));
        }
        float2 a0 = unpk2(acc0), a1 = unpk2(acc1);
        ((float4*)sAcc)[kx*16 + c] = make_float4(a0.x, a0.y, a1.x, a1.y);
    }
    __syncthreads();
    if (tid < 384) {   // stage 2: per-mode complex channel mix -> sMix
        int kx = tid >> 4, o = tid & 15;
        float2 dv[2];
#pragma unroll
        for (int kzi = 0; kzi < 2; kzi++) {
            const float2* Wp = g_W + ((size_t)((kx*24 + ky)*12 + k0 + kzi)) * 256;
            float2 acc = make_float2(0.f, 0.f);
#pragma unroll
            for (int i = 0; i < 16; i++) {
                float2 av = sAcc[(kx*16 + i)*2 + kzi];
                float2 w  = Wp[i*16 + o];
                acc.x += av.x*w.x - av.y*w.y;
                acc.y += av.x*w.y + av.y*w.x;
            }
            dv[kzi] = acc;
        }
        ((float4*)sMix)[kx*16 + o] = make_float4(dv[0].x, dv[0].y, dv[1].x, dv[1].y);
    }
    __syncthreads();

    {   // stage 3: inverse X DFT (parity); thread = (o, x1); full 512
        int o = tid >> 5, x1 = tid & 31;
        const u64* stX64 = (const u64*)stX;
        u64 Se[2], So[2];
        Se[0] = Se[1] = So[0] = So[1] = 0ull;
#pragma unroll 4
        for (int kx = 0; kx < 24; kx++) {
            u64 t1 = stX64[kx*33 + x1];
            float2 f = unpk2(t1);
            u64 t2 = pk2(-f.y, f.x);
            u64* tgt = (kx & 1) ? So : Se;
            const float2* dm = sMix + (kx*16 + o)*2;
#pragma unroll
            for (int kzi = 0; kzi < 2; kzi++) {
                float2 d = dm[kzi];                 // broadcast within warp
                fma2(tgt[kzi], t1, pk2(d.x, d.x));
                fma2(tgt[kzi], t2, pk2(d.y, d.y));
            }
        }
        float2 se0 = unpk2(Se[0]), so0 = unpk2(So[0]);
        float2 se1 = unpk2(Se[1]), so1 = unpk2(So[1]);
        float4* base = (float4*)(g_Bf + (size_t)((b*16 + o)*24 + ky)*768);  // [(bo*24+ky)*64+x][kz]
        base[(x1*12 + k0) >> 1]        = make_float4(se0.x + so0.x, se0.y + so0.y,
                                                    se1.x + so1.x, se1.y + so1.y);
        base[((x1 + 32)*12 + k0) >> 1] = make_float4(se0.x - so0.x, se0.y - so0.y,
                                                    se1.x - so1.x, se1.y - so1.y);
    }
}

// ---------------- kD2: fused inv-Y + inv-T + ReLU + 16x16 mix + bias ----------------
// block = (b, xx); 512 threads; y in 4 chunks; plain sE + deferred rotation;
// double-buffered sF -> ONE barrier per chunk; 97.5 KB dyn smem, 2 blocks/SM
#define KD2_SMEM ((4608 + 6144 + 792 + 384 + 256 + 8)*8)
__global__ void __launch_bounds__(512, 2) kD2(const float* __restrict__ lo_w,
                                              const float* __restrict__ lo_b,
                                              float* __restrict__ out) {
    extern __shared__ u64 sm[];
    u64* sE  = sm;                 // [c*288 + ky*12 + kz] packed (re,im)
    u64* sF  = sE + 4608;          // 2 x 3072: [(buf)*3072 + (c*16 + line)*12 + k]
    u64* sT1 = sF + 6144;          // (c,s) inv twiddles, pad 33
    u64* sTi = sT1 + 792;          // inv-T (A,B)
    u64* sWq = sTi + 384;          // lo_w dup-packed
    float* sB = (float*)(sWq + 256);

    int tid = threadIdx.x;
    int b = blockIdx.x >> 6, xx = blockIdx.x & 63;

    for (int i = tid; i < 4608; i += 512) {
        int c = i / 288, r = i % 288;              // r = ky*12 + kz
        int ky = r / 12, kz = r % 12;
        sE[i] = ((const u64*)g_Bf)[((size_t)((b*16 + c)*24 + ky)*64 + xx)*12 + kz];
    }
    for (int i = tid; i < 792; i += 512) sT1[i] = ((const u64*)g_twXY)[i];
    for (int i = tid; i < 384; i += 512) sTi[i] = ((const u64*)g_twTi2)[i];
    if (tid < 256) { float w = lo_w[tid]; sWq[tid] = pk2(w, w); }
    if (tid < 16)  sB[tid] = lo_b[tid];
    __syncthreads();

    int c  = tid >> 5;                 // phase-1 channel (warp-uniform)
    int l  = (tid >> 2) & 7;           // phase-1 y1 local
    int q  = tid & 3;                  // phase-1 kz triple
    int k0 = q * 3;
    int w    = tid >> 5;               // phase-2 warp = line
    int lane = tid & 31;

    for (int a = 0; a < 4; a++) {
        int buf = (a & 1) * 3072;
        // ---- phase 1: inverse Y (parity, deferred rotation), 16 lines into sF[buf] ----
        {
            int y1 = 8*a + l;
            const u64* E = sE + c*288 + k0;
            u64 SeA[3], SeB[3], SoA[3], SoB[3];
#pragma unroll
            for (int z = 0; z < 3; z++) { SeA[z]=0ull; SeB[z]=0ull; SoA[z]=0ull; SoB[z]=0ull; }
#pragma unroll 4
            for (int ky = 0; ky < 24; ky++) {
                u64 t1 = sT1[ky*33 + y1];
                const u64* e = E + ky*12;
                if (ky & 1) {
#pragma unroll
                    for (int z = 0; z < 3; z++) {
                        float2 d = unpk2(e[z]);
                        fma2(SoA[z], t1, pk2(d.x, d.x));
                        fma2(SoB[z], t1, pk2(d.y, d.y));
                    }
                } else {
#pragma unroll
                    for (int z = 0; z < 3; z++) {
                        float2 d = unpk2(e[z]);
                        fma2(SeA[z], t1, pk2(d.x, d.x));
                        fma2(SeB[z], t1, pk2(d.y, d.y));
                    }
                }
            }
#pragma unroll
            for (int z = 0; z < 3; z++) {
                // Σ d*(c,s)-pair -> apply rotation to B once: out = A + (-B.y, B.x)
                float2 aE = unpk2(SeA[z]), bE = unpk2(SeB[z]);
                float2 se = make_float2(aE.x - bE.y, aE.y + bE.x);
                float2 aO = unpk2(SoA[z]), bO = unpk2(SoB[z]);
                float2 so = make_float2(aO.x - bO.y, aO.y + bO.x);
                sF[buf + (c*16 + l)*12 + k0 + z]     = pk2(se.x + so.x, se.y + so.y);
                sF[buf + (c*16 + l + 8)*12 + k0 + z] = pk2(se.x - so.x, se.y - so.y);
            }
        }
        __syncthreads();

        // ---- phase 2: inverse T (parity) + ReLU + packed 1x1 mix; warp = line ----
        // (no trailing barrier: next chunk's phase-1 writes the OTHER sF buffer)
        {
            int y = 8*a + (w & 7) + ((w & 8) ? 32 : 0);
            u64 p[16];
#pragma unroll
            for (int qt = 0; qt < 4; qt++) {
                u64 aE[4], aO[4];
                aE[0]=aE[1]=aE[2]=aE[3]=0ull;
                aO[0]=aO[1]=aO[2]=aO[3]=0ull;
#pragma unroll
                for (int k = 0; k < 12; k++) {
                    u64 ti = sTi[k*32 + lane];
#pragma unroll
                    for (int c4 = 0; c4 < 4; c4++) {
                        u64 f = sF[buf + ((qt*4 + c4)*16 + w)*12 + k];   // warp-uniform broadcast
                        if (k & 1) fma2(aO[c4], f, ti);
                        else       fma2(aE[c4], f, ti);
                    }
                }
#pragma unroll
                for (int c4 = 0; c4 < 4; c4++) {
                    float2 e = unpk2(aE[c4]), o = unpk2(aO[c4]);
                    float Ev = e.x + e.y, Ov = o.x + o.y;
                    p[qt*4 + c4] = pk2(fmaxf(Ev + Ov, 0.f), fmaxf(Ev - Ov, 0.f));
                }
            }
#pragma unroll
            for (int o = 0; o < 16; o++) {
                u64 acc = pk2(sB[o], sB[o]);
#pragma unroll
                for (int cc = 0; cc < 16; cc++) fma2(acc, sWq[o*16 + cc], p[cc]);
                float2 rv = unpk2(acc);
                float* dst = out + (((size_t)(b*16 + o)*64 + xx)*64 + y)*64;
                dst[lane]      = rv.x;
                dst[lane + 32] = rv.y;
            }
        }
    }
}

// ---------------- launch ----------------
extern "C" void kernel_launch(void* const* d_in, const int* in_sizes, int n_in,
                              void* d_out, int out_size) {
    const float* x    = (const float*)d_in[0];
    const float* w1   = (const float*)d_in[1];
    const float* w2   = (const float*)d_in[2];
    const float* w3   = (const float*)d_in[3];
    const float* w4   = (const float*)d_in[4];
    const float* lo_w = (const float*)d_in[5];
    const float* lo_b = (const float*)d_in[6];
    float* out = (float*)d_out;

    cudaFuncSetAttribute(kA2, cudaFuncAttributeMaxDynamicSharedMemorySize, KA2_SMEM);
    cudaFuncSetAttribute(kD2, cudaFuncAttributeMaxDynamicSharedMemorySize, KD2_SMEM);

    k_initrepack<<<145, 256>>>(w1, w2, w3, w4);
    kA2<<<4096, 256, KA2_SMEM>>>(x);                 // T 64->12 + Y 64->24 fused
    kBC<<<1152, 512>>>();                            // X 64->24 + channel mix + X 24->64 fused
    kD2<<<512, 512, KD2_SMEM>>>(lo_w, lo_b, out);    // Y 24->64 + T 12->64 + relu + 1x1 fused
}